// round 3
// baseline (speedup 1.0000x reference)
#include <cuda_runtime.h>
#include <math.h>

#define B_  4
#define S_  2048
#define D_  1024
#define H_  16
#define HD_ 64
#define PAD 68   // smem row pitch (floats) for 64-wide tiles: bank-conflict-free

// Scratch (allocation-free rule: __device__ globals)
__device__ float g_Q[(size_t)B_ * S_ * D_];
__device__ float g_K[(size_t)B_ * S_ * D_];
__device__ float g_V[(size_t)B_ * S_ * D_];
__device__ float g_A[(size_t)B_ * S_ * D_];

// ---------------------------------------------------------------------------
// C[M,N] = A[M,K] @ W[K,N] + bias.  128x128 tile, BK=8, 8x8 per thread.
// M=8192, N=K=1024 (all multiples of tile sizes: no bounds checks).
// ---------------------------------------------------------------------------
__global__ __launch_bounds__(256, 2)
void sgemm_bias(const float* __restrict__ A, const float* __restrict__ W,
                const float* __restrict__ bias, float* __restrict__ C,
                int M, int N, int K)
{
    __shared__ float As[8][132];   // transposed A tile, padded
    __shared__ float Bs[8][132];

    const int t    = threadIdx.x;
    const int tx   = t & 15;
    const int ty   = t >> 4;
    const int row0 = blockIdx.y * 128;
    const int col0 = blockIdx.x * 128;

    const int a_row = t >> 1;          // 0..127
    const int a_k4  = (t & 1) * 4;     // 0 or 4
    const int b_k   = t >> 5;          // 0..7
    const int b_c4  = (t & 31) * 4;    // 0..124

    float acc[8][8] = {};

    for (int k0 = 0; k0 < K; k0 += 8) {
        float4 a4 = *(const float4*)&A[(size_t)(row0 + a_row) * K + k0 + a_k4];
        float4 b4 = *(const float4*)&W[(size_t)(k0 + b_k) * N + col0 + b_c4];
        As[a_k4 + 0][a_row] = a4.x;
        As[a_k4 + 1][a_row] = a4.y;
        As[a_k4 + 2][a_row] = a4.z;
        As[a_k4 + 3][a_row] = a4.w;
        *(float4*)&Bs[b_k][b_c4] = b4;
        __syncthreads();

        #pragma unroll
        for (int kk = 0; kk < 8; kk++) {
            float ar[8], br[8];
            *(float4*)&ar[0] = *(const float4*)&As[kk][ty * 8];
            *(float4*)&ar[4] = *(const float4*)&As[kk][ty * 8 + 4];
            *(float4*)&br[0] = *(const float4*)&Bs[kk][tx * 8];
            *(float4*)&br[4] = *(const float4*)&Bs[kk][tx * 8 + 4];
            #pragma unroll
            for (int i = 0; i < 8; i++)
                #pragma unroll
                for (int j = 0; j < 8; j++)
                    acc[i][j] += ar[i] * br[j];
        }
        __syncthreads();
    }

    #pragma unroll
    for (int i = 0; i < 8; i++) {
        const int r = row0 + ty * 8 + i;
        #pragma unroll
        for (int j = 0; j < 8; j += 4) {
            const int c = col0 + tx * 8 + j;
            float4 o;
            o.x = acc[i][j + 0] + bias[c + 0];
            o.y = acc[i][j + 1] + bias[c + 1];
            o.z = acc[i][j + 2] + bias[c + 2];
            o.w = acc[i][j + 3] + bias[c + 3];
            *(float4*)&C[(size_t)r * N + c] = o;
        }
    }
}

// ---------------------------------------------------------------------------
// RoPE over the full model dim (pairs (2i, 2i+1), half = D/2 = 512), applied
// in-place to Q and K. Angles in fp64 (ref computes fp32; both within ~1e-4
// of true value -> well inside the 1e-3 budget).
// ---------------------------------------------------------------------------
__global__ void rope_kernel(float* __restrict__ Q, float* __restrict__ Kp)
{
    const int idx = blockIdx.x * blockDim.x + threadIdx.x;  // exact grid
    const int i   = idx & (D_ / 2 - 1);   // pair index 0..511
    const int row = idx >> 9;             // b*S + s
    const int s   = row & (S_ - 1);

    const double inv = exp((double)i * (-9.210340371976184 / (double)(D_ / 2)));
    const double ang = (double)s * inv;
    double sd, cd;
    sincos(ang, &sd, &cd);
    const float c  = (float)cd;
    const float sn = (float)sd;

    const size_t base = (size_t)row * D_ + 2 * i;
    const float q1 = Q[base], q2 = Q[base + 1];
    Q[base]     = q1 * c - q2 * sn;
    Q[base + 1] = q1 * sn + q2 * c;
    const float k1 = Kp[base], k2 = Kp[base + 1];
    Kp[base]     = k1 * c - k2 * sn;
    Kp[base + 1] = k1 * sn + k2 * c;
}

// ---------------------------------------------------------------------------
// Causal flash attention. One block per (q-tile of 64, head, batch).
// 256 threads: thread (r = t>>2, g = t&3). Q row in registers (64 f32).
// Scores: j = 4*jj + g (strided -> conflict-free smem with PAD=68).
// Online softmax replicated across the 4-lane quad via shfl_xor.
// ---------------------------------------------------------------------------
__global__ __launch_bounds__(256, 2)
void attn_kernel(const float* __restrict__ Q, const float* __restrict__ Kg,
                 const float* __restrict__ Vg, float* __restrict__ Og)
{
    extern __shared__ float sm[];
    float* Ks = sm;                 // [64][PAD]
    float* Vs = sm + 64 * PAD;      // [64][PAD]
    float* Ps = sm + 2 * 64 * PAD;  // [64][PAD], also Q staging

    const int qb = blockIdx.x, h = blockIdx.y, b = blockIdx.z;
    const int t  = threadIdx.x;
    const int r  = t >> 2;          // row 0..63
    const int g  = t & 3;           // quad lane
    const size_t bh = (size_t)b * S_ * D_ + (size_t)h * HD_;
    const int q0 = qb * 64;
    const int lr = t >> 2;          // load row
    const int c0 = (t & 3) * 16;    // load col chunk

    // Stage Q tile through Ps (coalesced), then copy own row to registers.
    {
        const float* gq = Q + bh + (size_t)(q0 + lr) * D_ + c0;
        #pragma unroll
        for (int q4 = 0; q4 < 16; q4 += 4)
            *(float4*)&Ps[lr * PAD + c0 + q4] = *(const float4*)(gq + q4);
    }
    __syncthreads();
    float qreg[64];
    #pragma unroll
    for (int d = 0; d < 64; d++) qreg[d] = Ps[r * PAD + d];
    __syncthreads();

    float m = -1e30f, l = 0.f;
    float o[16];
    #pragma unroll
    for (int c = 0; c < 16; c++) o[c] = 0.f;

    for (int kb = 0; kb <= qb; kb++) {
        const float* gk = Kg + bh + (size_t)(kb * 64 + lr) * D_ + c0;
        const float* gv = Vg + bh + (size_t)(kb * 64 + lr) * D_ + c0;
        #pragma unroll
        for (int q4 = 0; q4 < 16; q4 += 4) {
            *(float4*)&Ks[lr * PAD + c0 + q4] = *(const float4*)(gk + q4);
            *(float4*)&Vs[lr * PAD + c0 + q4] = *(const float4*)(gv + q4);
        }
        __syncthreads();

        // Scores for this thread's 16 strided columns.
        float sc[16];
        #pragma unroll
        for (int jj = 0; jj < 16; jj++) {
            const int j = 4 * jj + g;
            float a = 0.f;
            #pragma unroll
            for (int d4 = 0; d4 < 16; d4++) {
                float4 kv = *(const float4*)&Ks[j * PAD + 4 * d4];
                a += qreg[4 * d4 + 0] * kv.x + qreg[4 * d4 + 1] * kv.y
                   + qreg[4 * d4 + 2] * kv.z + qreg[4 * d4 + 3] * kv.w;
            }
            a *= 0.125f;                        // 1/sqrt(64)
            if (kb == qb && j > r) a = -1e30f;  // causal mask (diag tile)
            sc[jj] = a;
        }

        // Online softmax (quad-replicated stats).
        float mt = sc[0];
        #pragma unroll
        for (int jj = 1; jj < 16; jj++) mt = fmaxf(mt, sc[jj]);
        mt = fmaxf(mt, __shfl_xor_sync(0xffffffffu, mt, 1));
        mt = fmaxf(mt, __shfl_xor_sync(0xffffffffu, mt, 2));
        const float mnew = fmaxf(m, mt);
        const float corr = __expf(m - mnew);
        float lt = 0.f;
        #pragma unroll
        for (int jj = 0; jj < 16; jj++) {
            const float p = __expf(sc[jj] - mnew);
            lt += p;
            Ps[r * PAD + 4 * jj + g] = p;
        }
        lt += __shfl_xor_sync(0xffffffffu, lt, 1);
        lt += __shfl_xor_sync(0xffffffffu, lt, 2);
        l = l * corr + lt;
        m = mnew;
        #pragma unroll
        for (int c = 0; c < 16; c++) o[c] *= corr;
        __syncwarp();   // Ps row written by own quad (same warp)

        // O += P @ V  (this thread: 16 contiguous cols at g*16)
        #pragma unroll 4
        for (int j = 0; j < 64; j++) {
            const float p = Ps[r * PAD + j];
            #pragma unroll
            for (int c4 = 0; c4 < 4; c4++) {
                float4 v = *(const float4*)&Vs[j * PAD + g * 16 + 4 * c4];
                o[4 * c4 + 0] += p * v.x;
                o[4 * c4 + 1] += p * v.y;
                o[4 * c4 + 2] += p * v.z;
                o[4 * c4 + 3] += p * v.w;
            }
        }
        __syncthreads();
    }

    const float invl = 1.f / l;
    float* go = Og + bh + (size_t)(q0 + r) * D_ + g * 16;
    #pragma unroll
    for (int c4 = 0; c4 < 4; c4++) {
        float4 v;
        v.x = o[4 * c4 + 0] * invl;
        v.y = o[4 * c4 + 1] * invl;
        v.z = o[4 * c4 + 2] * invl;
        v.w = o[4 * c4 + 3] * invl;
        *(float4*)(go + 4 * c4) = v;
    }
}

// ---------------------------------------------------------------------------
extern "C" void kernel_launch(void* const* d_in, const int* in_sizes, int n_in,
                              void* d_out, int out_size)
{
    const float* X  = (const float*)d_in[0];
    const float* Wq = (const float*)d_in[1];
    const float* bq = (const float*)d_in[2];
    const float* Wk = (const float*)d_in[3];
    const float* bk = (const float*)d_in[4];
    const float* Wv = (const float*)d_in[5];
    const float* bv = (const float*)d_in[6];
    const float* Wo = (const float*)d_in[7];
    const float* bo = (const float*)d_in[8];
    float* out = (float*)d_out;

    float *Qp, *Kp, *Vp, *Ap;
    cudaGetSymbolAddress((void**)&Qp, g_Q);
    cudaGetSymbolAddress((void**)&Kp, g_K);
    cudaGetSymbolAddress((void**)&Vp, g_V);
    cudaGetSymbolAddress((void**)&Ap, g_A);

    const int M = B_ * S_, N = D_, K = D_;
    dim3 gemm_grid(N / 128, M / 128);

    sgemm_bias<<<gemm_grid, 256>>>(X, Wq, bq, Qp, M, N, K);
    sgemm_bias<<<gemm_grid, 256>>>(X, Wk, bk, Kp, M, N, K);
    sgemm_bias<<<gemm_grid, 256>>>(X, Wv, bv, Vp, M, N, K);

    const int rope_total = B_ * S_ * (D_ / 2);
    rope_kernel<<<rope_total / 256, 256>>>(Qp, Kp);

    const int attn_smem = 3 * 64 * PAD * sizeof(float);  // 52224 B
    cudaFuncSetAttribute(attn_kernel,
                         cudaFuncAttributeMaxDynamicSharedMemorySize, attn_smem);
    attn_kernel<<<dim3(S_ / 64, H_, B_), 256, attn_smem>>>(Qp, Kp, Vp, Ap);

    sgemm_bias<<<gemm_grid, 256>>>(Ap, Wo, bo, out, M, N, K);
}

// round 5
// speedup vs baseline: 1.3613x; 1.3613x over previous
#include <cuda_runtime.h>
#include <cuda_bf16.h>
#include <cstdint>
#include <math.h>

#define B_  4
#define S_  2048
#define D_  1024
#define H_  16
#define HD_ 64
#define PAD 68

// ---------------------------------------------------------------------------
// Scratch (__device__ globals: allocation-free rule)
// ---------------------------------------------------------------------------
__device__ float g_Q[(size_t)B_ * S_ * D_];
__device__ float g_K[(size_t)B_ * S_ * D_];
__device__ float g_V[(size_t)B_ * S_ * D_];
__device__ float g_A[(size_t)B_ * S_ * D_];
__device__ __nv_bfloat16 g_Xh[(size_t)B_ * S_ * D_];   // activation hi (reused for attn out)
__device__ __nv_bfloat16 g_Xl[(size_t)B_ * S_ * D_];   // activation lo
__device__ __nv_bfloat16 g_Wh[4][(size_t)D_ * D_];     // Wq,Wk,Wv,Wo hi ([K,N] layout)
__device__ __nv_bfloat16 g_Wl[4][(size_t)D_ * D_];     // ... lo

__device__ __forceinline__ uint32_t smem_u32(const void* p) {
    uint32_t a;
    asm("{ .reg .u64 t; cvta.to.shared.u64 t, %1; cvt.u32.u64 %0, t; }" : "=r"(a) : "l"(p));
    return a;
}

__device__ __forceinline__ void cp16(uint32_t s, const void* g) {
    asm volatile("cp.async.cg.shared.global [%0], [%1], 16;" :: "r"(s), "l"(g) : "memory");
}

#define LDSM_X4(r0, r1, r2, r3, a)                                              \
    asm volatile("ldmatrix.sync.aligned.m8n8.x4.shared.b16 {%0,%1,%2,%3}, [%4];" \
        : "=r"(r0), "=r"(r1), "=r"(r2), "=r"(r3) : "r"(a))

#define LDSM_X4T(r0, r1, r2, r3, a)                                                   \
    asm volatile("ldmatrix.sync.aligned.m8n8.x4.trans.shared.b16 {%0,%1,%2,%3}, [%4];" \
        : "=r"(r0), "=r"(r1), "=r"(r2), "=r"(r3) : "r"(a))

__device__ __forceinline__ void mma16816(float* d, const uint32_t* a, const uint32_t* b) {
    asm volatile(
        "mma.sync.aligned.m16n8k16.row.col.f32.bf16.bf16.f32 "
        "{%0,%1,%2,%3}, {%4,%5,%6,%7}, {%8,%9}, {%0,%1,%2,%3};"
        : "+f"(d[0]), "+f"(d[1]), "+f"(d[2]), "+f"(d[3])
        : "r"(a[0]), "r"(a[1]), "r"(a[2]), "r"(a[3]), "r"(b[0]), "r"(b[1]));
}

// ---------------------------------------------------------------------------
// Split fp32 -> bf16 hi/lo (hi = rn(x), lo = rn(x - hi))
// ---------------------------------------------------------------------------
__global__ void split_bf16(const float4* __restrict__ src,
                           __nv_bfloat16* __restrict__ hi,
                           __nv_bfloat16* __restrict__ lo)
{
    const int i = blockIdx.x * blockDim.x + threadIdx.x;   // exact grid
    float4 x = src[i];
    union { __nv_bfloat16 b[4]; uint2 u; } h, l;
    h.b[0] = __float2bfloat16_rn(x.x); l.b[0] = __float2bfloat16_rn(x.x - __bfloat162float(h.b[0]));
    h.b[1] = __float2bfloat16_rn(x.y); l.b[1] = __float2bfloat16_rn(x.y - __bfloat162float(h.b[1]));
    h.b[2] = __float2bfloat16_rn(x.z); l.b[2] = __float2bfloat16_rn(x.z - __bfloat162float(h.b[2]));
    h.b[3] = __float2bfloat16_rn(x.w); l.b[3] = __float2bfloat16_rn(x.w - __bfloat162float(h.b[3]));
    *(uint2*)&hi[(size_t)i * 4] = h.u;
    *(uint2*)&lo[(size_t)i * 4] = l.u;
}

// ---------------------------------------------------------------------------
// bf16x3 mma.sync GEMM:  C[M,N] = (Ah+Al)[M,K] @ (Bh+Bl)[K,N] + bias
// CTA 128x128, BK=32, 8 warps (2x4 grid of 64x32 warp tiles), 2-stage cp.async.
// ---------------------------------------------------------------------------
#define BM 128
#define BN 128
#define BK 32
#define APITCH 40     // bf16 elems per A smem row (128B conflict-free ldmatrix)
#define BPITCH 136    // bf16 elems per B smem row
#define A_BYTES (BM * APITCH * 2)                 // 10240
#define B_BYTES (BK * BPITCH * 2)                 // 8704
#define STG     (2 * A_BYTES + 2 * B_BYTES)       // 37888
#define GEMM_SMEM (2 * STG)                       // 75776

__global__ __launch_bounds__(256)
void gemm_bf16x3(const __nv_bfloat16* __restrict__ Ah, const __nv_bfloat16* __restrict__ Al,
                 const __nv_bfloat16* __restrict__ Bh, const __nv_bfloat16* __restrict__ Bl,
                 const float* __restrict__ bias, float* __restrict__ C,
                 int M, int N, int K)
{
    extern __shared__ char smraw[];
    const uint32_t sbase = smem_u32(smraw);
    const int t    = threadIdx.x;
    const int lane = t & 31;
    const int wid  = t >> 5;
    const int wm   = wid & 1;    // 0..1 -> 64-row slab
    const int wn   = wid >> 1;   // 0..3 -> 32-col slab
    const int row0 = blockIdx.y * BM;
    const int col0 = blockIdx.x * BN;

    float acc[4][4][4];
    #pragma unroll
    for (int i = 0; i < 4; i++)
        #pragma unroll
        for (int j = 0; j < 4; j++)
            #pragma unroll
            for (int v = 0; v < 4; v++) acc[i][j][v] = 0.f;

    // ---- stage loader: A tile [128][32], B tile [32][128], hi+lo ----
    auto load_stage = [&](int s, int k0) {
        const uint32_t sb = sbase + (uint32_t)s * STG;
        #pragma unroll
        for (int it = 0; it < 2; it++) {
            const int idx = it * 256 + t;          // 0..511
            const int m   = idx >> 2;              // A row
            const int ca  = idx & 3;               // A 16B col
            const size_t ga = (size_t)(row0 + m) * K + k0 + ca * 8;
            const uint32_t soa = (uint32_t)(m * APITCH * 2 + ca * 16);
            cp16(sb + soa,           Ah + ga);
            cp16(sb + A_BYTES + soa, Al + ga);
            const int kr = idx >> 4;               // B row (k)
            const int cb = idx & 15;               // B 16B col
            const size_t gb = (size_t)(k0 + kr) * N + col0 + cb * 8;
            const uint32_t sob = (uint32_t)(kr * BPITCH * 2 + cb * 16);
            cp16(sb + 2 * A_BYTES + sob,           Bh + gb);
            cp16(sb + 2 * A_BYTES + B_BYTES + sob, Bl + gb);
        }
        asm volatile("cp.async.commit_group;" ::: "memory");
    };

    const int NCH = K / BK;
    load_stage(0, 0);

    for (int ch = 0; ch < NCH; ch++) {
        if (ch + 1 < NCH) {
            load_stage((ch + 1) & 1, (ch + 1) * BK);
            asm volatile("cp.async.wait_group 1;" ::: "memory");
        } else {
            asm volatile("cp.async.wait_group 0;" ::: "memory");
        }
        __syncthreads();

        const uint32_t sb  = sbase + (uint32_t)(ch & 1) * STG;
        const uint32_t aAh = sb;
        const uint32_t aAl = sb + A_BYTES;
        const uint32_t aBh = sb + 2 * A_BYTES;
        const uint32_t aBl = aBh + B_BYTES;

        #pragma unroll
        for (int ks = 0; ks < 2; ks++) {
            uint32_t ah[4][4], al[4][4], bh[4][2], bl[4][2];

            const int mr = wm * 64 + (lane & 15);
            const int kc = ks * 16 + (lane >> 4) * 8;
            #pragma unroll
            for (int i = 0; i < 4; i++) {
                const uint32_t off = (uint32_t)(((mr + i * 16) * APITCH + kc) * 2);
                LDSM_X4(ah[i][0], ah[i][1], ah[i][2], ah[i][3], aAh + off);
                LDSM_X4(al[i][0], al[i][1], al[i][2], al[i][3], aAl + off);
            }

            const int kr = ks * 16 + (lane & 15);
            const int nc = wn * 32 + (lane >> 4) * 8;
            #pragma unroll
            for (int jp = 0; jp < 2; jp++) {
                const uint32_t off = (uint32_t)((kr * BPITCH + nc + jp * 16) * 2);
                LDSM_X4T(bh[2 * jp][0], bh[2 * jp][1], bh[2 * jp + 1][0], bh[2 * jp + 1][1], aBh + off);
                LDSM_X4T(bl[2 * jp][0], bl[2 * jp][1], bl[2 * jp + 1][0], bl[2 * jp + 1][1], aBl + off);
            }

            #pragma unroll
            for (int i = 0; i < 4; i++)
                #pragma unroll
                for (int j = 0; j < 4; j++) {
                    mma16816(acc[i][j], ah[i], bh[j]);
                    mma16816(acc[i][j], ah[i], bl[j]);
                    mma16816(acc[i][j], al[i], bh[j]);
                }
        }
        __syncthreads();
    }

    // ---- epilogue ----
    const int gr = lane >> 2;
    const int gc = (lane & 3) * 2;
    #pragma unroll
    for (int i = 0; i < 4; i++) {
        #pragma unroll
        for (int j = 0; j < 4; j++) {
            const int r = row0 + wm * 64 + i * 16 + gr;
            const int c = col0 + wn * 32 + j * 8 + gc;
            const float b0 = bias[c], b1 = bias[c + 1];
            float2 v0 = make_float2(acc[i][j][0] + b0, acc[i][j][1] + b1);
            float2 v1 = make_float2(acc[i][j][2] + b0, acc[i][j][3] + b1);
            *(float2*)&C[(size_t)r * N + c]       = v0;
            *(float2*)&C[(size_t)(r + 8) * N + c] = v1;
        }
    }
}

// ---------------------------------------------------------------------------
// RoPE, fp32 pipeline
// ---------------------------------------------------------------------------
__global__ void rope_kernel(float* __restrict__ Q, float* __restrict__ Kp)
{
    const int idx = blockIdx.x * blockDim.x + threadIdx.x;
    const int i   = idx & (D_ / 2 - 1);
    const int row = idx >> 9;
    const int s   = row & (S_ - 1);

    const float inv = exp2f((float)i * (-13.287712379549449f / (float)(D_ / 2)));
    const float ang = (float)s * inv;
    float sn, c;
    sincosf(ang, &sn, &c);

    const size_t base = (size_t)row * D_ + 2 * i;
    const float q1 = Q[base], q2 = Q[base + 1];
    Q[base]     = q1 * c - q2 * sn;
    Q[base + 1] = q1 * sn + q2 * c;
    const float k1 = Kp[base], k2 = Kp[base + 1];
    Kp[base]     = k1 * c - k2 * sn;
    Kp[base + 1] = k1 * sn + k2 * c;
}

// ---------------------------------------------------------------------------
// Causal flash attention (R2 version + longest-first q-tile order)
// ---------------------------------------------------------------------------
__global__ __launch_bounds__(256, 2)
void attn_kernel(const float* __restrict__ Q, const float* __restrict__ Kg,
                 const float* __restrict__ Vg, float* __restrict__ Og)
{
    extern __shared__ float sm[];
    float* Ks = sm;
    float* Vs = sm + 64 * PAD;
    float* Ps = sm + 2 * 64 * PAD;

    const int qb = gridDim.x - 1 - blockIdx.x;   // longest tiles first
    const int h = blockIdx.y, b = blockIdx.z;
    const int t  = threadIdx.x;
    const int r  = t >> 2;
    const int g  = t & 3;
    const size_t bh = (size_t)b * S_ * D_ + (size_t)h * HD_;
    const int q0 = qb * 64;
    const int lr = t >> 2;
    const int c0 = (t & 3) * 16;

    {
        const float* gq = Q + bh + (size_t)(q0 + lr) * D_ + c0;
        #pragma unroll
        for (int q4 = 0; q4 < 16; q4 += 4)
            *(float4*)&Ps[lr * PAD + c0 + q4] = *(const float4*)(gq + q4);
    }
    __syncthreads();
    float qreg[64];
    #pragma unroll
    for (int d = 0; d < 64; d++) qreg[d] = Ps[r * PAD + d];
    __syncthreads();

    float m = -1e30f, l = 0.f;
    float o[16];
    #pragma unroll
    for (int c = 0; c < 16; c++) o[c] = 0.f;

    for (int kb = 0; kb <= qb; kb++) {
        const float* gk = Kg + bh + (size_t)(kb * 64 + lr) * D_ + c0;
        const float* gv = Vg + bh + (size_t)(kb * 64 + lr) * D_ + c0;
        #pragma unroll
        for (int q4 = 0; q4 < 16; q4 += 4) {
            *(float4*)&Ks[lr * PAD + c0 + q4] = *(const float4*)(gk + q4);
            *(float4*)&Vs[lr * PAD + c0 + q4] = *(const float4*)(gv + q4);
        }
        __syncthreads();

        float sc[16];
        #pragma unroll
        for (int jj = 0; jj < 16; jj++) {
            const int j = 4 * jj + g;
            float a = 0.f;
            #pragma unroll
            for (int d4 = 0; d4 < 16; d4++) {
                float4 kv = *(const float4*)&Ks[j * PAD + 4 * d4];
                a += qreg[4 * d4 + 0] * kv.x + qreg[4 * d4 + 1] * kv.y
                   + qreg[4 * d4 + 2] * kv.z + qreg[4 * d4 + 3] * kv.w;
            }
            a *= 0.125f;
            if (kb == qb && j > r) a = -1e30f;
            sc[jj] = a;
        }

        float mt = sc[0];
        #pragma unroll
        for (int jj = 1; jj < 16; jj++) mt = fmaxf(mt, sc[jj]);
        mt = fmaxf(mt, __shfl_xor_sync(0xffffffffu, mt, 1));
        mt = fmaxf(mt, __shfl_xor_sync(0xffffffffu, mt, 2));
        const float mnew = fmaxf(m, mt);
        const float corr = __expf(m - mnew);
        float lt = 0.f;
        #pragma unroll
        for (int jj = 0; jj < 16; jj++) {
            const float p = __expf(sc[jj] - mnew);
            lt += p;
            Ps[r * PAD + 4 * jj + g] = p;
        }
        lt += __shfl_xor_sync(0xffffffffu, lt, 1);
        lt += __shfl_xor_sync(0xffffffffu, lt, 2);
        l = l * corr + lt;
        m = mnew;
        #pragma unroll
        for (int c = 0; c < 16; c++) o[c] *= corr;
        __syncwarp();

        #pragma unroll 4
        for (int j = 0; j < 64; j++) {
            const float p = Ps[r * PAD + j];
            #pragma unroll
            for (int c4 = 0; c4 < 4; c4++) {
                float4 v = *(const float4*)&Vs[j * PAD + g * 16 + 4 * c4];
                o[4 * c4 + 0] += p * v.x;
                o[4 * c4 + 1] += p * v.y;
                o[4 * c4 + 2] += p * v.z;
                o[4 * c4 + 3] += p * v.w;
            }
        }
        __syncthreads();
    }

    const float invl = 1.f / l;
    float* go = Og + bh + (size_t)(q0 + r) * D_ + g * 16;
    #pragma unroll
    for (int c4 = 0; c4 < 4; c4++) {
        float4 v;
        v.x = o[4 * c4 + 0] * invl;
        v.y = o[4 * c4 + 1] * invl;
        v.z = o[4 * c4 + 2] * invl;
        v.w = o[4 * c4 + 3] * invl;
        *(float4*)(go + 4 * c4) = v;
    }
}

// ---------------------------------------------------------------------------
extern "C" void kernel_launch(void* const* d_in, const int* in_sizes, int n_in,
                              void* d_out, int out_size)
{
    const float* X  = (const float*)d_in[0];
    const float* Wq = (const float*)d_in[1];
    const float* bq = (const float*)d_in[2];
    const float* Wk = (const float*)d_in[3];
    const float* bk = (const float*)d_in[4];
    const float* Wv = (const float*)d_in[5];
    const float* bv = (const float*)d_in[6];
    const float* Wo = (const float*)d_in[7];
    const float* bo = (const float*)d_in[8];
    float* out = (float*)d_out;

    float *Qp, *Kp, *Vp, *Ap;
    __nv_bfloat16 *Xh, *Xl, *Wh, *Wl;
    cudaGetSymbolAddress((void**)&Qp, g_Q);
    cudaGetSymbolAddress((void**)&Kp, g_K);
    cudaGetSymbolAddress((void**)&Vp, g_V);
    cudaGetSymbolAddress((void**)&Ap, g_A);
    cudaGetSymbolAddress((void**)&Xh, g_Xh);
    cudaGetSymbolAddress((void**)&Xl, g_Xl);
    cudaGetSymbolAddress((void**)&Wh, g_Wh);
    cudaGetSymbolAddress((void**)&Wl, g_Wl);
    const size_t WSZ = (size_t)D_ * D_;

    const int M = B_ * S_;
    const int nvec4 = M * D_ / 4;      // activation float4 count
    const int wvec4 = D_ * D_ / 4;     // weight float4 count

    // --- split operands to bf16 hi/lo ---
    split_bf16<<<nvec4 / 256, 256>>>((const float4*)X, Xh, Xl);
    split_bf16<<<wvec4 / 256, 256>>>((const float4*)Wq, Wh + 0 * WSZ, Wl + 0 * WSZ);
    split_bf16<<<wvec4 / 256, 256>>>((const float4*)Wk, Wh + 1 * WSZ, Wl + 1 * WSZ);
    split_bf16<<<wvec4 / 256, 256>>>((const float4*)Wv, Wh + 2 * WSZ, Wl + 2 * WSZ);
    split_bf16<<<wvec4 / 256, 256>>>((const float4*)Wo, Wh + 3 * WSZ, Wl + 3 * WSZ);

    // --- Q/K/V projections (tensor-core bf16x3) ---
    cudaFuncSetAttribute(gemm_bf16x3,
                         cudaFuncAttributeMaxDynamicSharedMemorySize, GEMM_SMEM);
    dim3 ggrid(D_ / BN, M / BM);
    gemm_bf16x3<<<ggrid, 256, GEMM_SMEM>>>(Xh, Xl, Wh + 0 * WSZ, Wl + 0 * WSZ, bq, Qp, M, D_, D_);
    gemm_bf16x3<<<ggrid, 256, GEMM_SMEM>>>(Xh, Xl, Wh + 1 * WSZ, Wl + 1 * WSZ, bk, Kp, M, D_, D_);
    gemm_bf16x3<<<ggrid, 256, GEMM_SMEM>>>(Xh, Xl, Wh + 2 * WSZ, Wl + 2 * WSZ, bv, Vp, M, D_, D_);

    // --- RoPE ---
    const int rope_total = B_ * S_ * (D_ / 2);
    rope_kernel<<<rope_total / 256, 256>>>(Qp, Kp);

    // --- attention ---
    const int attn_smem = 3 * 64 * PAD * sizeof(float);
    cudaFuncSetAttribute(attn_kernel,
                         cudaFuncAttributeMaxDynamicSharedMemorySize, attn_smem);
    attn_kernel<<<dim3(S_ / 64, H_, B_), 256, attn_smem>>>(Qp, Kp, Vp, Ap);

    // --- output projection ---
    split_bf16<<<nvec4 / 256, 256>>>((const float4*)Ap, Xh, Xl);
    gemm_bf16x3<<<ggrid, 256, GEMM_SMEM>>>(Xh, Xl, Wh + 3 * WSZ, Wl + 3 * WSZ, bo, out, M, D_, D_);
}

// round 7
// speedup vs baseline: 5.3257x; 3.9123x over previous
#include <cuda_runtime.h>
#include <cuda_bf16.h>
#include <cstdint>
#include <math.h>

#define B_  4
#define S_  2048
#define D_  1024
#define H_  16
#define HD_ 64

// ---------------------------------------------------------------------------
// Scratch (__device__ globals: allocation-free rule)
// ---------------------------------------------------------------------------
__device__ float g_Q[(size_t)B_ * S_ * D_];
__device__ float g_K[(size_t)B_ * S_ * D_];
__device__ float g_V[(size_t)B_ * S_ * D_];
__device__ __nv_bfloat16 g_Xh[(size_t)B_ * S_ * D_];   // activations hi (X, later attn out)
__device__ __nv_bfloat16 g_Xl[(size_t)B_ * S_ * D_];
__device__ __nv_bfloat16 g_Qh[(size_t)B_ * S_ * D_];
__device__ __nv_bfloat16 g_Ql[(size_t)B_ * S_ * D_];
__device__ __nv_bfloat16 g_Kh[(size_t)B_ * S_ * D_];
__device__ __nv_bfloat16 g_Kl[(size_t)B_ * S_ * D_];
__device__ __nv_bfloat16 g_Vh[(size_t)B_ * S_ * D_];
__device__ __nv_bfloat16 g_Vl[(size_t)B_ * S_ * D_];
__device__ __nv_bfloat16 g_Wh[4][(size_t)D_ * D_];
__device__ __nv_bfloat16 g_Wl[4][(size_t)D_ * D_];

__device__ __forceinline__ uint32_t smem_u32(const void* p) {
    uint32_t a;
    asm("{ .reg .u64 t; cvta.to.shared.u64 t, %1; cvt.u32.u64 %0, t; }" : "=r"(a) : "l"(p));
    return a;
}
__device__ __forceinline__ void cp16(uint32_t s, const void* g) {
    asm volatile("cp.async.cg.shared.global [%0], [%1], 16;" :: "r"(s), "l"(g) : "memory");
}
#define LDSM_X4(r0, r1, r2, r3, a)                                              \
    asm volatile("ldmatrix.sync.aligned.m8n8.x4.shared.b16 {%0,%1,%2,%3}, [%4];" \
        : "=r"(r0), "=r"(r1), "=r"(r2), "=r"(r3) : "r"(a))
#define LDSM_X4T(r0, r1, r2, r3, a)                                                   \
    asm volatile("ldmatrix.sync.aligned.m8n8.x4.trans.shared.b16 {%0,%1,%2,%3}, [%4];" \
        : "=r"(r0), "=r"(r1), "=r"(r2), "=r"(r3) : "r"(a))

__device__ __forceinline__ void mma16816(float* d, const uint32_t* a, const uint32_t* b) {
    asm volatile(
        "mma.sync.aligned.m16n8k16.row.col.f32.bf16.bf16.f32 "
        "{%0,%1,%2,%3}, {%4,%5,%6,%7}, {%8,%9}, {%0,%1,%2,%3};"
        : "+f"(d[0]), "+f"(d[1]), "+f"(d[2]), "+f"(d[3])
        : "r"(a[0]), "r"(a[1]), "r"(a[2]), "r"(a[3]), "r"(b[0]), "r"(b[1]));
}

// pack2(lo, hi): bf16x2 with 'lo' in the low half
__device__ __forceinline__ uint32_t pack2(float lo, float hi) {
    uint32_t r;
    asm("cvt.rn.bf16x2.f32 %0, %1, %2;" : "=r"(r) : "f"(hi), "f"(lo));
    return r;
}
// residual pack: lo-parts of (v0,v1) relative to hi pack hp
__device__ __forceinline__ uint32_t pack2_lo(uint32_t hp, float v0, float v1) {
    float r0 = v0 - __uint_as_float(hp << 16);
    float r1 = v1 - __uint_as_float(hp & 0xffff0000u);
    return pack2(r0, r1);
}

// ---------------------------------------------------------------------------
// Split fp32 -> bf16 hi/lo
// ---------------------------------------------------------------------------
__global__ void split_bf16(const float4* __restrict__ src,
                           __nv_bfloat16* __restrict__ hi,
                           __nv_bfloat16* __restrict__ lo)
{
    const int i = blockIdx.x * blockDim.x + threadIdx.x;
    float4 x = src[i];
    uint2 h, l;
    h.x = pack2(x.x, x.y); l.x = pack2(x.x - __uint_as_float(h.x << 16),
                                       x.y - __uint_as_float(h.x & 0xffff0000u));
    h.y = pack2(x.z, x.w); l.y = pack2(x.z - __uint_as_float(h.y << 16),
                                       x.w - __uint_as_float(h.y & 0xffff0000u));
    *(uint2*)&hi[(size_t)i * 4] = h;
    *(uint2*)&lo[(size_t)i * 4] = l;
}

// ---------------------------------------------------------------------------
// bf16x3 mma.sync GEMM (validated R4)
// ---------------------------------------------------------------------------
#define BM 128
#define BN 128
#define BK 32
#define APITCH 40
#define BPITCH 136
#define A_BYTES (BM * APITCH * 2)
#define B_BYTES (BK * BPITCH * 2)
#define STG     (2 * A_BYTES + 2 * B_BYTES)
#define GEMM_SMEM (2 * STG)

__global__ __launch_bounds__(256)
void gemm_bf16x3(const __nv_bfloat16* __restrict__ Ah, const __nv_bfloat16* __restrict__ Al,
                 const __nv_bfloat16* __restrict__ Bh, const __nv_bfloat16* __restrict__ Bl,
                 const float* __restrict__ bias, float* __restrict__ C,
                 int M, int N, int K)
{
    extern __shared__ char smraw[];
    const uint32_t sbase = smem_u32(smraw);
    const int t    = threadIdx.x;
    const int lane = t & 31;
    const int wid  = t >> 5;
    const int wm   = wid & 1;
    const int wn   = wid >> 1;
    const int row0 = blockIdx.y * BM;
    const int col0 = blockIdx.x * BN;

    float acc[4][4][4];
    #pragma unroll
    for (int i = 0; i < 4; i++)
        #pragma unroll
        for (int j = 0; j < 4; j++)
            #pragma unroll
            for (int v = 0; v < 4; v++) acc[i][j][v] = 0.f;

    auto load_stage = [&](int s, int k0) {
        const uint32_t sb = sbase + (uint32_t)s * STG;
        #pragma unroll
        for (int it = 0; it < 2; it++) {
            const int idx = it * 256 + t;
            const int m   = idx >> 2;
            const int ca  = idx & 3;
            const size_t ga = (size_t)(row0 + m) * K + k0 + ca * 8;
            const uint32_t soa = (uint32_t)(m * APITCH * 2 + ca * 16);
            cp16(sb + soa,           Ah + ga);
            cp16(sb + A_BYTES + soa, Al + ga);
            const int kr = idx >> 4;
            const int cb = idx & 15;
            const size_t gb = (size_t)(k0 + kr) * N + col0 + cb * 8;
            const uint32_t sob = (uint32_t)(kr * BPITCH * 2 + cb * 16);
            cp16(sb + 2 * A_BYTES + sob,           Bh + gb);
            cp16(sb + 2 * A_BYTES + B_BYTES + sob, Bl + gb);
        }
        asm volatile("cp.async.commit_group;" ::: "memory");
    };

    const int NCH = K / BK;
    load_stage(0, 0);

    for (int ch = 0; ch < NCH; ch++) {
        if (ch + 1 < NCH) {
            load_stage((ch + 1) & 1, (ch + 1) * BK);
            asm volatile("cp.async.wait_group 1;" ::: "memory");
        } else {
            asm volatile("cp.async.wait_group 0;" ::: "memory");
        }
        __syncthreads();

        const uint32_t sb  = sbase + (uint32_t)(ch & 1) * STG;
        const uint32_t aAh = sb;
        const uint32_t aAl = sb + A_BYTES;
        const uint32_t aBh = sb + 2 * A_BYTES;
        const uint32_t aBl = aBh + B_BYTES;

        #pragma unroll
        for (int ks = 0; ks < 2; ks++) {
            uint32_t ah[4][4], al[4][4], bh[4][2], bl[4][2];

            const int mr = wm * 64 + (lane & 15);
            const int kc = ks * 16 + (lane >> 4) * 8;
            #pragma unroll
            for (int i = 0; i < 4; i++) {
                const uint32_t off = (uint32_t)(((mr + i * 16) * APITCH + kc) * 2);
                LDSM_X4(ah[i][0], ah[i][1], ah[i][2], ah[i][3], aAh + off);
                LDSM_X4(al[i][0], al[i][1], al[i][2], al[i][3], aAl + off);
            }

            const int kr = ks * 16 + (lane & 15);
            const int nc = wn * 32 + (lane >> 4) * 8;
            #pragma unroll
            for (int jp = 0; jp < 2; jp++) {
                const uint32_t off = (uint32_t)((kr * BPITCH + nc + jp * 16) * 2);
                LDSM_X4T(bh[2 * jp][0], bh[2 * jp][1], bh[2 * jp + 1][0], bh[2 * jp + 1][1], aBh + off);
                LDSM_X4T(bl[2 * jp][0], bl[2 * jp][1], bl[2 * jp + 1][0], bl[2 * jp + 1][1], aBl + off);
            }

            #pragma unroll
            for (int i = 0; i < 4; i++)
                #pragma unroll
                for (int j = 0; j < 4; j++) {
                    mma16816(acc[i][j], ah[i], bh[j]);
                    mma16816(acc[i][j], ah[i], bl[j]);
                    mma16816(acc[i][j], al[i], bh[j]);
                }
        }
        __syncthreads();
    }

    const int gr = lane >> 2;
    const int gc = (lane & 3) * 2;
    #pragma unroll
    for (int i = 0; i < 4; i++) {
        #pragma unroll
        for (int j = 0; j < 4; j++) {
            const int r = row0 + wm * 64 + i * 16 + gr;
            const int c = col0 + wn * 32 + j * 8 + gc;
            const float b0 = bias[c], b1 = bias[c + 1];
            float2 v0 = make_float2(acc[i][j][0] + b0, acc[i][j][1] + b1);
            float2 v1 = make_float2(acc[i][j][2] + b0, acc[i][j][3] + b1);
            *(float2*)&C[(size_t)r * N + c]       = v0;
            *(float2*)&C[(size_t)(r + 8) * N + c] = v1;
        }
    }
}

// ---------------------------------------------------------------------------
// RoPE (fp32) + bf16 hi/lo split of Q and K
// ---------------------------------------------------------------------------
__global__ void rope_split(const float* __restrict__ Q, const float* __restrict__ Kp,
                           __nv_bfloat16* __restrict__ Qh, __nv_bfloat16* __restrict__ Ql,
                           __nv_bfloat16* __restrict__ Kh, __nv_bfloat16* __restrict__ Kl)
{
    const int idx = blockIdx.x * blockDim.x + threadIdx.x;
    const int i   = idx & (D_ / 2 - 1);
    const int row = idx >> 9;
    const int s   = row & (S_ - 1);

    const float inv = exp2f((float)i * (-13.287712379549449f / (float)(D_ / 2)));
    const float ang = (float)s * inv;
    float sn, c;
    sincosf(ang, &sn, &c);

    const size_t base = (size_t)row * D_ + 2 * i;
    const float q1 = Q[base], q2 = Q[base + 1];
    const float rq1 = q1 * c - q2 * sn, rq2 = q1 * sn + q2 * c;
    const uint32_t qp = pack2(rq1, rq2);
    *(uint32_t*)&Qh[base] = qp;
    *(uint32_t*)&Ql[base] = pack2_lo(qp, rq1, rq2);

    const float k1 = Kp[base], k2 = Kp[base + 1];
    const float rk1 = k1 * c - k2 * sn, rk2 = k1 * sn + k2 * c;
    const uint32_t kp = pack2(rk1, rk2);
    *(uint32_t*)&Kh[base] = kp;
    *(uint32_t*)&Kl[base] = pack2_lo(kp, rk1, rk2);
}

// ---------------------------------------------------------------------------
// Tensor-core causal flash attention, bf16x3 compensated.
// CTA = 64 q-rows x (head, batch). 4 warps; warp w owns q-rows w*16..w*16+15.
// K tile [64 tok][64 d] per iter, 2-stage cp.async pipeline.
// Output written as bf16 hi/lo directly into g_Xh/g_Xl for the final GEMM.
// ---------------------------------------------------------------------------
#define KPITCH 72                    // bf16 elems per smem row
#define KROW_B (KPITCH * 2)          // 144 bytes
#define TILE_B (64 * KROW_B)         // 9216
#define ASTG   (4 * TILE_B)          // Kh,Kl,Vh,Vl per stage = 36864
#define ATTN_SMEM (2 * ASTG)         // 73728

__global__ __launch_bounds__(128, 2)
void attn_mma(const __nv_bfloat16* __restrict__ Qh, const __nv_bfloat16* __restrict__ Ql,
              const __nv_bfloat16* __restrict__ Kh, const __nv_bfloat16* __restrict__ Kl,
              const __nv_bfloat16* __restrict__ Vh, const __nv_bfloat16* __restrict__ Vl,
              __nv_bfloat16* __restrict__ Oh, __nv_bfloat16* __restrict__ Ol)
{
    extern __shared__ char smraw[];
    const uint32_t sb0 = smem_u32(smraw);
    const int t = threadIdx.x, lane = t & 31, w = t >> 5;
    const int qb = gridDim.x - 1 - blockIdx.x;   // longest first
    const int h = blockIdx.y, b = blockIdx.z;
    const size_t bh = (size_t)b * S_ * D_ + (size_t)h * HD_;
    const int q0 = qb * 64;

    // ---- stage Q tile through stage-1 buffer, load A-fragments ----
    const uint32_t qbuf = sb0 + ASTG;
    #pragma unroll
    for (int it = 0; it < 4; it++) {
        const int idx = it * 128 + t;            // 0..511
        const int r = idx >> 3, c = idx & 7;
        const size_t g = bh + (size_t)(q0 + r) * D_ + c * 8;
        const uint32_t so = (uint32_t)(r * KROW_B + c * 16);
        cp16(qbuf + so,          Qh + g);
        cp16(qbuf + TILE_B + so, Ql + g);
    }
    asm volatile("cp.async.commit_group;" ::: "memory");
    asm volatile("cp.async.wait_group 0;" ::: "memory");
    __syncthreads();

    uint32_t qhf[4][4], qlf[4][4];
    {
        const int mr = w * 16 + (lane & 15);
        #pragma unroll
        for (int ks = 0; ks < 4; ks++) {
            const uint32_t off = (uint32_t)(mr * KROW_B + ks * 32 + (lane >> 4) * 16);
            LDSM_X4(qhf[ks][0], qhf[ks][1], qhf[ks][2], qhf[ks][3], qbuf + off);
            LDSM_X4(qlf[ks][0], qlf[ks][1], qlf[ks][2], qlf[ks][3], qbuf + TILE_B + off);
        }
    }
    __syncthreads();

    // ---- K/V stage loader ----
    auto load_kv = [&](int kb) {
        const uint32_t sb = sb0 + (uint32_t)(kb & 1) * ASTG;
        #pragma unroll
        for (int it = 0; it < 4; it++) {
            const int idx = it * 128 + t;
            const int r = idx >> 3, c = idx & 7;
            const size_t g = bh + (size_t)(kb * 64 + r) * D_ + c * 8;
            const uint32_t so = (uint32_t)(r * KROW_B + c * 16);
            cp16(sb + so,              Kh + g);
            cp16(sb + TILE_B + so,     Kl + g);
            cp16(sb + 2 * TILE_B + so, Vh + g);
            cp16(sb + 3 * TILE_B + so, Vl + g);
        }
        asm volatile("cp.async.commit_group;" ::: "memory");
    };
    load_kv(0);

    const int gr  = lane >> 2;
    const int gc2 = (lane & 3) * 2;
    const int row0g = q0 + w * 16 + gr;
    const int row1g = row0g + 8;

    float m0 = -1e30f, m1 = -1e30f, l0 = 0.f, l1 = 0.f;
    float oa[8][4];
    #pragma unroll
    for (int nf = 0; nf < 8; nf++)
        #pragma unroll
        for (int v = 0; v < 4; v++) oa[nf][v] = 0.f;

    for (int kb = 0; kb <= qb; kb++) {
        if (kb < qb) {
            load_kv(kb + 1);
            asm volatile("cp.async.wait_group 1;" ::: "memory");
        } else {
            asm volatile("cp.async.wait_group 0;" ::: "memory");
        }
        __syncthreads();
        const uint32_t sb = sb0 + (uint32_t)(kb & 1) * ASTG;

        // ---- S = Q K^T (x3 terms) ----
        float sa[8][4];
        #pragma unroll
        for (int nf = 0; nf < 8; nf++)
            #pragma unroll
            for (int v = 0; v < 4; v++) sa[nf][v] = 0.f;

        #pragma unroll
        for (int ks = 0; ks < 4; ks++) {
            uint32_t kbh[8][2], kbl[8][2];
            #pragma unroll
            for (int nf16 = 0; nf16 < 4; nf16++) {
                const uint32_t off = (uint32_t)((nf16 * 16 + (lane & 15)) * KROW_B
                                                + ks * 32 + (lane >> 4) * 16);
                uint32_t r0, r1, r2, r3;
                LDSM_X4(r0, r1, r2, r3, sb + off);
                kbh[2 * nf16][0] = r0; kbh[2 * nf16][1] = r2;
                kbh[2 * nf16 + 1][0] = r1; kbh[2 * nf16 + 1][1] = r3;
                LDSM_X4(r0, r1, r2, r3, sb + TILE_B + off);
                kbl[2 * nf16][0] = r0; kbl[2 * nf16][1] = r2;
                kbl[2 * nf16 + 1][0] = r1; kbl[2 * nf16 + 1][1] = r3;
            }
            #pragma unroll
            for (int nf = 0; nf < 8; nf++) {
                mma16816(sa[nf], qhf[ks], kbh[nf]);
                mma16816(sa[nf], qhf[ks], kbl[nf]);
                mma16816(sa[nf], qlf[ks], kbh[nf]);
            }
        }

        // ---- scale + causal mask ----
        #pragma unroll
        for (int nf = 0; nf < 8; nf++)
            #pragma unroll
            for (int v = 0; v < 4; v++) sa[nf][v] *= 0.125f;

        if (kb == qb) {
            #pragma unroll
            for (int nf = 0; nf < 8; nf++) {
                const int col = kb * 64 + nf * 8 + gc2;
                if (col     > row0g) sa[nf][0] = -1e30f;
                if (col + 1 > row0g) sa[nf][1] = -1e30f;
                if (col     > row1g) sa[nf][2] = -1e30f;
                if (col + 1 > row1g) sa[nf][3] = -1e30f;
            }
        }

        // ---- online softmax (2 rows per thread) ----
        float mt0 = sa[0][0], mt1 = sa[0][2];
        #pragma unroll
        for (int nf = 0; nf < 8; nf++) {
            mt0 = fmaxf(mt0, fmaxf(sa[nf][0], sa[nf][1]));
            mt1 = fmaxf(mt1, fmaxf(sa[nf][2], sa[nf][3]));
        }
        mt0 = fmaxf(mt0, __shfl_xor_sync(0xffffffffu, mt0, 1));
        mt0 = fmaxf(mt0, __shfl_xor_sync(0xffffffffu, mt0, 2));
        mt1 = fmaxf(mt1, __shfl_xor_sync(0xffffffffu, mt1, 1));
        mt1 = fmaxf(mt1, __shfl_xor_sync(0xffffffffu, mt1, 2));

        const float mn0 = fmaxf(m0, mt0), mn1 = fmaxf(m1, mt1);
        const float c0 = __expf(m0 - mn0), c1 = __expf(m1 - mn1);
        float s0 = 0.f, s1 = 0.f;
        #pragma unroll
        for (int nf = 0; nf < 8; nf++) {
            sa[nf][0] = __expf(sa[nf][0] - mn0); s0 += sa[nf][0];
            sa[nf][1] = __expf(sa[nf][1] - mn0); s0 += sa[nf][1];
            sa[nf][2] = __expf(sa[nf][2] - mn1); s1 += sa[nf][2];
            sa[nf][3] = __expf(sa[nf][3] - mn1); s1 += sa[nf][3];
        }
        s0 += __shfl_xor_sync(0xffffffffu, s0, 1);
        s0 += __shfl_xor_sync(0xffffffffu, s0, 2);
        s1 += __shfl_xor_sync(0xffffffffu, s1, 1);
        s1 += __shfl_xor_sync(0xffffffffu, s1, 2);
        l0 = l0 * c0 + s0;  l1 = l1 * c1 + s1;
        m0 = mn0;           m1 = mn1;

        #pragma unroll
        for (int nf = 0; nf < 8; nf++) {
            oa[nf][0] *= c0; oa[nf][1] *= c0;
            oa[nf][2] *= c1; oa[nf][3] *= c1;
        }

        // ---- O += P V (x3 terms) ----
        #pragma unroll
        for (int ks = 0; ks < 4; ks++) {
            uint32_t ph[4], pl[4];
            ph[0] = pack2(sa[2 * ks][0],     sa[2 * ks][1]);
            pl[0] = pack2_lo(ph[0], sa[2 * ks][0], sa[2 * ks][1]);
            ph[1] = pack2(sa[2 * ks][2],     sa[2 * ks][3]);
            pl[1] = pack2_lo(ph[1], sa[2 * ks][2], sa[2 * ks][3]);
            ph[2] = pack2(sa[2 * ks + 1][0], sa[2 * ks + 1][1]);
            pl[2] = pack2_lo(ph[2], sa[2 * ks + 1][0], sa[2 * ks + 1][1]);
            ph[3] = pack2(sa[2 * ks + 1][2], sa[2 * ks + 1][3]);
            pl[3] = pack2_lo(ph[3], sa[2 * ks + 1][2], sa[2 * ks + 1][3]);

            uint32_t vbh[8][2], vbl[8][2];
            #pragma unroll
            for (int nf16 = 0; nf16 < 4; nf16++) {
                const uint32_t off = (uint32_t)((ks * 16 + (lane & 15)) * KROW_B
                                                + nf16 * 32 + (lane >> 4) * 16);
                LDSM_X4T(vbh[2 * nf16][0], vbh[2 * nf16][1],
                         vbh[2 * nf16 + 1][0], vbh[2 * nf16 + 1][1], sb + 2 * TILE_B + off);
                LDSM_X4T(vbl[2 * nf16][0], vbl[2 * nf16][1],
                         vbl[2 * nf16 + 1][0], vbl[2 * nf16 + 1][1], sb + 3 * TILE_B + off);
            }
            #pragma unroll
            for (int nf = 0; nf < 8; nf++) {
                mma16816(oa[nf], ph, vbh[nf]);
                mma16816(oa[nf], ph, vbl[nf]);
                mma16816(oa[nf], pl, vbh[nf]);
            }
        }
        __syncthreads();
    }

    // ---- epilogue: normalize, split bf16 hi/lo, store ----
    const float iv0 = 1.f / l0, iv1 = 1.f / l1;
    #pragma unroll
    for (int nf = 0; nf < 8; nf++) {
        const size_t a0 = bh + (size_t)(q0 + w * 16 + gr) * D_ + nf * 8 + gc2;
        const size_t a1 = a0 + 8 * D_;
        const float o00 = oa[nf][0] * iv0, o01 = oa[nf][1] * iv0;
        const float o10 = oa[nf][2] * iv1, o11 = oa[nf][3] * iv1;
        const uint32_t hp0 = pack2(o00, o01);
        const uint32_t hp1 = pack2(o10, o11);
        *(uint32_t*)&Oh[a0] = hp0;
        *(uint32_t*)&Ol[a0] = pack2_lo(hp0, o00, o01);
        *(uint32_t*)&Oh[a1] = hp1;
        *(uint32_t*)&Ol[a1] = pack2_lo(hp1, o10, o11);
    }
}

// ---------------------------------------------------------------------------
extern "C" void kernel_launch(void* const* d_in, const int* in_sizes, int n_in,
                              void* d_out, int out_size)
{
    const float* X  = (const float*)d_in[0];
    const float* Wq = (const float*)d_in[1];
    const float* bq = (const float*)d_in[2];
    const float* Wk = (const float*)d_in[3];
    const float* bk = (const float*)d_in[4];
    const float* Wv = (const float*)d_in[5];
    const float* bv = (const float*)d_in[6];
    const float* Wo = (const float*)d_in[7];
    const float* bo = (const float*)d_in[8];
    float* out = (float*)d_out;

    float *Qp, *Kp, *Vp;
    __nv_bfloat16 *Xh, *Xl, *Wh, *Wl, *Qh, *Ql, *Khb, *Klb, *Vh, *Vl;
    cudaGetSymbolAddress((void**)&Qp,  g_Q);
    cudaGetSymbolAddress((void**)&Kp,  g_K);
    cudaGetSymbolAddress((void**)&Vp,  g_V);
    cudaGetSymbolAddress((void**)&Xh,  g_Xh);
    cudaGetSymbolAddress((void**)&Xl,  g_Xl);
    cudaGetSymbolAddress((void**)&Wh,  g_Wh);
    cudaGetSymbolAddress((void**)&Wl,  g_Wl);
    cudaGetSymbolAddress((void**)&Qh,  g_Qh);
    cudaGetSymbolAddress((void**)&Ql,  g_Ql);
    cudaGetSymbolAddress((void**)&Khb, g_Kh);
    cudaGetSymbolAddress((void**)&Klb, g_Kl);
    cudaGetSymbolAddress((void**)&Vh,  g_Vh);
    cudaGetSymbolAddress((void**)&Vl,  g_Vl);
    const size_t WSZ = (size_t)D_ * D_;

    const int M = B_ * S_;
    const int nvec4 = M * D_ / 4;
    const int wvec4 = D_ * D_ / 4;

    // split operands
    split_bf16<<<nvec4 / 256, 256>>>((const float4*)X, Xh, Xl);
    split_bf16<<<wvec4 / 256, 256>>>((const float4*)Wq, Wh + 0 * WSZ, Wl + 0 * WSZ);
    split_bf16<<<wvec4 / 256, 256>>>((const float4*)Wk, Wh + 1 * WSZ, Wl + 1 * WSZ);
    split_bf16<<<wvec4 / 256, 256>>>((const float4*)Wv, Wh + 2 * WSZ, Wl + 2 * WSZ);
    split_bf16<<<wvec4 / 256, 256>>>((const float4*)Wo, Wh + 3 * WSZ, Wl + 3 * WSZ);

    // Q/K/V projections
    cudaFuncSetAttribute(gemm_bf16x3,
                         cudaFuncAttributeMaxDynamicSharedMemorySize, GEMM_SMEM);
    dim3 ggrid(D_ / BN, M / BM);
    gemm_bf16x3<<<ggrid, 256, GEMM_SMEM>>>(Xh, Xl, Wh + 0 * WSZ, Wl + 0 * WSZ, bq, Qp, M, D_, D_);
    gemm_bf16x3<<<ggrid, 256, GEMM_SMEM>>>(Xh, Xl, Wh + 1 * WSZ, Wl + 1 * WSZ, bk, Kp, M, D_, D_);
    gemm_bf16x3<<<ggrid, 256, GEMM_SMEM>>>(Xh, Xl, Wh + 2 * WSZ, Wl + 2 * WSZ, bv, Vp, M, D_, D_);

    // RoPE + bf16 split of Q/K; split V
    const int rope_total = B_ * S_ * (D_ / 2);
    rope_split<<<rope_total / 256, 256>>>(Qp, Kp, Qh, Ql, Khb, Klb);
    split_bf16<<<nvec4 / 256, 256>>>((const float4*)Vp, Vh, Vl);

    // tensor-core attention -> writes bf16 hi/lo into Xh/Xl
    cudaFuncSetAttribute(attn_mma,
                         cudaFuncAttributeMaxDynamicSharedMemorySize, ATTN_SMEM);
    attn_mma<<<dim3(S_ / 64, H_, B_), 128, ATTN_SMEM>>>(Qh, Ql, Khb, Klb, Vh, Vl, Xh, Xl);

    // output projection
    gemm_bf16x3<<<ggrid, 256, GEMM_SMEM>>>(Xh, Xl, Wh + 3 * WSZ, Wl + 3 * WSZ, bo, out, M, D_, D_);
}

// round 9
// speedup vs baseline: 5.3381x; 1.0023x over previous
#include <cuda_runtime.h>
#include <cuda_bf16.h>
#include <cstdint>
#include <math.h>

#define B_  4
#define S_  2048
#define D_  1024
#define H_  16
#define HD_ 64

// ---------------------------------------------------------------------------
// Scratch (__device__ globals: allocation-free rule)
// ---------------------------------------------------------------------------
__device__ __nv_bfloat16 g_Xh[(size_t)B_ * S_ * D_];   // X hi, later attn-out hi
__device__ __nv_bfloat16 g_Xl[(size_t)B_ * S_ * D_];
__device__ __nv_bfloat16 g_Qh[(size_t)B_ * S_ * D_];
__device__ __nv_bfloat16 g_Ql[(size_t)B_ * S_ * D_];
__device__ __nv_bfloat16 g_Kh[(size_t)B_ * S_ * D_];
__device__ __nv_bfloat16 g_Kl[(size_t)B_ * S_ * D_];
__device__ __nv_bfloat16 g_Vh[(size_t)B_ * S_ * D_];
__device__ __nv_bfloat16 g_Vl[(size_t)B_ * S_ * D_];
__device__ __nv_bfloat16 g_Wh[4][(size_t)D_ * D_];
__device__ __nv_bfloat16 g_Wl[4][(size_t)D_ * D_];
__device__ float2 g_tab[(size_t)S_ * (D_ / 2)];        // (cos,sin)[s][pair]

__device__ __forceinline__ uint32_t smem_u32(const void* p) {
    uint32_t a;
    asm("{ .reg .u64 t; cvta.to.shared.u64 t, %1; cvt.u32.u64 %0, t; }" : "=r"(a) : "l"(p));
    return a;
}
__device__ __forceinline__ void cp16(uint32_t s, const void* g) {
    asm volatile("cp.async.cg.shared.global [%0], [%1], 16;" :: "r"(s), "l"(g) : "memory");
}
#define LDSM_X4(r0, r1, r2, r3, a)                                              \
    asm volatile("ldmatrix.sync.aligned.m8n8.x4.shared.b16 {%0,%1,%2,%3}, [%4];" \
        : "=r"(r0), "=r"(r1), "=r"(r2), "=r"(r3) : "r"(a))
#define LDSM_X4T(r0, r1, r2, r3, a)                                                   \
    asm volatile("ldmatrix.sync.aligned.m8n8.x4.trans.shared.b16 {%0,%1,%2,%3}, [%4];" \
        : "=r"(r0), "=r"(r1), "=r"(r2), "=r"(r3) : "r"(a))

__device__ __forceinline__ void mma16816(float* d, const uint32_t* a, const uint32_t* b) {
    asm volatile(
        "mma.sync.aligned.m16n8k16.row.col.f32.bf16.bf16.f32 "
        "{%0,%1,%2,%3}, {%4,%5,%6,%7}, {%8,%9}, {%0,%1,%2,%3};"
        : "+f"(d[0]), "+f"(d[1]), "+f"(d[2]), "+f"(d[3])
        : "r"(a[0]), "r"(a[1]), "r"(a[2]), "r"(a[3]), "r"(b[0]), "r"(b[1]));
}

__device__ __forceinline__ uint32_t pack2(float lo, float hi) {
    uint32_t r;
    asm("cvt.rn.bf16x2.f32 %0, %1, %2;" : "=r"(r) : "f"(hi), "f"(lo));
    return r;
}
__device__ __forceinline__ uint32_t pack2_lo(uint32_t hp, float v0, float v1) {
    float r0 = v0 - __uint_as_float(hp << 16);
    float r1 = v1 - __uint_as_float(hp & 0xffff0000u);
    return pack2(r0, r1);
}

// ---------------------------------------------------------------------------
// RoPE cos/sin table: tab[s][p] = (cos(s*inv(p)), sin(s*inv(p)))
// ---------------------------------------------------------------------------
__global__ void rope_table(float2* __restrict__ tab)
{
    const int idx = blockIdx.x * blockDim.x + threadIdx.x;   // exact grid 1M
    const int p = idx & (D_ / 2 - 1);
    const int s = idx >> 9;
    const float inv = exp2f((float)p * (-13.287712379549449f / (float)(D_ / 2)));
    float sn, c;
    sincosf((float)s * inv, &sn, &c);
    tab[idx] = make_float2(c, sn);
}

// ---------------------------------------------------------------------------
// Split fp32 -> bf16 hi/lo (X only)
// ---------------------------------------------------------------------------
__global__ void split_bf16(const float4* __restrict__ src,
                           __nv_bfloat16* __restrict__ hi,
                           __nv_bfloat16* __restrict__ lo)
{
    const int i = blockIdx.x * blockDim.x + threadIdx.x;
    float4 x = src[i];
    uint2 h, l;
    h.x = pack2(x.x, x.y); l.x = pack2(x.x - __uint_as_float(h.x << 16),
                                       x.y - __uint_as_float(h.x & 0xffff0000u));
    h.y = pack2(x.z, x.w); l.y = pack2(x.z - __uint_as_float(h.y << 16),
                                       x.w - __uint_as_float(h.y & 0xffff0000u));
    *(uint2*)&hi[(size_t)i * 4] = h;
    *(uint2*)&lo[(size_t)i * 4] = l;
}

// All 4 weight splits in one launch (blockIdx.y selects matrix)
__global__ void split_w4(const float4* __restrict__ w0, const float4* __restrict__ w1,
                         const float4* __restrict__ w2, const float4* __restrict__ w3,
                         __nv_bfloat16* __restrict__ hi, __nv_bfloat16* __restrict__ lo)
{
    const int m = blockIdx.y;
    const float4* src = (m == 0) ? w0 : (m == 1) ? w1 : (m == 2) ? w2 : w3;
    const int i = blockIdx.x * blockDim.x + threadIdx.x;
    const size_t off = (size_t)m * D_ * D_ + (size_t)i * 4;
    float4 x = src[i];
    uint2 h, l;
    h.x = pack2(x.x, x.y); l.x = pack2(x.x - __uint_as_float(h.x << 16),
                                       x.y - __uint_as_float(h.x & 0xffff0000u));
    h.y = pack2(x.z, x.w); l.y = pack2(x.z - __uint_as_float(h.y << 16),
                                       x.w - __uint_as_float(h.y & 0xffff0000u));
    *(uint2*)&hi[off] = h;
    *(uint2*)&lo[off] = l;
}

// ---------------------------------------------------------------------------
// bf16x3 mma.sync GEMM, 3-stage cp.async pipeline.
// MODE 0: C = fp32 out + bias           (output projection)
// MODE 1: RoPE(out + bias) -> bf16 hi/lo (Q/K projections)
// MODE 2: (out + bias)     -> bf16 hi/lo (V projection)
// ---------------------------------------------------------------------------
#define BM 128
#define BN 128
#define BK 32
#define APITCH 40
#define BPITCH 136
#define A_BYTES (BM * APITCH * 2)
#define B_BYTES (BK * BPITCH * 2)
#define STG     (2 * A_BYTES + 2 * B_BYTES)   // 37888
#define NSTAGE  3
#define GEMM_SMEM (NSTAGE * STG)              // 113664

template<int MODE>
__global__ __launch_bounds__(256)
void gemm_bf16x3(const __nv_bfloat16* __restrict__ Ah, const __nv_bfloat16* __restrict__ Al,
                 const __nv_bfloat16* __restrict__ Bh, const __nv_bfloat16* __restrict__ Bl,
                 const float* __restrict__ bias, float* __restrict__ C,
                 __nv_bfloat16* __restrict__ Oh, __nv_bfloat16* __restrict__ Ol,
                 const float2* __restrict__ tab,
                 int M, int N, int K)
{
    extern __shared__ char smraw[];
    const uint32_t sbase = smem_u32(smraw);
    const int t    = threadIdx.x;
    const int lane = t & 31;
    const int wid  = t >> 5;
    const int wm   = wid & 1;
    const int wn   = wid >> 1;
    const int row0 = blockIdx.y * BM;
    const int col0 = blockIdx.x * BN;

    float acc[4][4][4];
    #pragma unroll
    for (int i = 0; i < 4; i++)
        #pragma unroll
        for (int j = 0; j < 4; j++)
            #pragma unroll
            for (int v = 0; v < 4; v++) acc[i][j][v] = 0.f;

    auto load_stage = [&](int s, int k0) {
        const uint32_t sb = sbase + (uint32_t)s * STG;
        #pragma unroll
        for (int it = 0; it < 2; it++) {
            const int idx = it * 256 + t;
            const int m   = idx >> 2;
            const int ca  = idx & 3;
            const size_t ga = (size_t)(row0 + m) * K + k0 + ca * 8;
            const uint32_t soa = (uint32_t)(m * APITCH * 2 + ca * 16);
            cp16(sb + soa,           Ah + ga);
            cp16(sb + A_BYTES + soa, Al + ga);
            const int kr = idx >> 4;
            const int cb = idx & 15;
            const size_t gb = (size_t)(k0 + kr) * N + col0 + cb * 8;
            const uint32_t sob = (uint32_t)(kr * BPITCH * 2 + cb * 16);
            cp16(sb + 2 * A_BYTES + sob,           Bh + gb);
            cp16(sb + 2 * A_BYTES + B_BYTES + sob, Bl + gb);
        }
        asm volatile("cp.async.commit_group;" ::: "memory");
    };

    const int NCH = K / BK;
    load_stage(0, 0);
    load_stage(1, BK);

    for (int ch = 0; ch < NCH; ch++) {
        if (ch + 2 < NCH) {
            load_stage((ch + 2) % NSTAGE, (ch + 2) * BK);
            asm volatile("cp.async.wait_group 2;" ::: "memory");
        } else {
            asm volatile("cp.async.wait_group 0;" ::: "memory");
        }
        __syncthreads();

        const uint32_t sb  = sbase + (uint32_t)(ch % NSTAGE) * STG;
        const uint32_t aAh = sb;
        const uint32_t aAl = sb + A_BYTES;
        const uint32_t aBh = sb + 2 * A_BYTES;
        const uint32_t aBl = aBh + B_BYTES;

        #pragma unroll
        for (int ks = 0; ks < 2; ks++) {
            uint32_t ah[4][4], al[4][4], bh[4][2], bl[4][2];

            const int mr = wm * 64 + (lane & 15);
            const int kc = ks * 16 + (lane >> 4) * 8;
            #pragma unroll
            for (int i = 0; i < 4; i++) {
                const uint32_t off = (uint32_t)(((mr + i * 16) * APITCH + kc) * 2);
                LDSM_X4(ah[i][0], ah[i][1], ah[i][2], ah[i][3], aAh + off);
                LDSM_X4(al[i][0], al[i][1], al[i][2], al[i][3], aAl + off);
            }

            const int kr = ks * 16 + (lane & 15);
            const int nc = wn * 32 + (lane >> 4) * 8;
            #pragma unroll
            for (int jp = 0; jp < 2; jp++) {
                const uint32_t off = (uint32_t)((kr * BPITCH + nc + jp * 16) * 2);
                LDSM_X4T(bh[2 * jp][0], bh[2 * jp][1], bh[2 * jp + 1][0], bh[2 * jp + 1][1], aBh + off);
                LDSM_X4T(bl[2 * jp][0], bl[2 * jp][1], bl[2 * jp + 1][0], bl[2 * jp + 1][1], aBl + off);
            }

            #pragma unroll
            for (int i = 0; i < 4; i++)
                #pragma unroll
                for (int j = 0; j < 4; j++) {
                    mma16816(acc[i][j], ah[i], bh[j]);
                    mma16816(acc[i][j], ah[i], bl[j]);
                    mma16816(acc[i][j], al[i], bh[j]);
                }
        }
        __syncthreads();
    }

    // ---- epilogue ----
    const int gr = lane >> 2;
    const int gc = (lane & 3) * 2;
    #pragma unroll
    for (int i = 0; i < 4; i++) {
        const int r0g = row0 + wm * 64 + i * 16 + gr;
        const int r1g = r0g + 8;
        #pragma unroll
        for (int j = 0; j < 4; j++) {
            const int c = col0 + wn * 32 + j * 8 + gc;
            const float b0 = bias[c], b1 = bias[c + 1];
            float v00 = acc[i][j][0] + b0, v01 = acc[i][j][1] + b1;
            float v10 = acc[i][j][2] + b0, v11 = acc[i][j][3] + b1;

            if (MODE == 0) {
                *(float2*)&C[(size_t)r0g * N + c] = make_float2(v00, v01);
                *(float2*)&C[(size_t)r1g * N + c] = make_float2(v10, v11);
            } else {
                if (MODE == 1) {   // RoPE on pair (c, c+1)
                    const int p = c >> 1;
                    const float2 cs0 = tab[(size_t)(r0g & (S_ - 1)) * (D_ / 2) + p];
                    const float2 cs1 = tab[(size_t)(r1g & (S_ - 1)) * (D_ / 2) + p];
                    float t0 = v00 * cs0.x - v01 * cs0.y;
                    float t1 = v00 * cs0.y + v01 * cs0.x;
                    v00 = t0; v01 = t1;
                    t0 = v10 * cs1.x - v11 * cs1.y;
                    t1 = v10 * cs1.y + v11 * cs1.x;
                    v10 = t0; v11 = t1;
                }
                const size_t a0 = (size_t)r0g * N + c;
                const size_t a1 = (size_t)r1g * N + c;
                const uint32_t h0 = pack2(v00, v01);
                const uint32_t h1 = pack2(v10, v11);
                *(uint32_t*)&Oh[a0] = h0;
                *(uint32_t*)&Ol[a0] = pack2_lo(h0, v00, v01);
                *(uint32_t*)&Oh[a1] = h1;
                *(uint32_t*)&Ol[a1] = pack2_lo(h1, v10, v11);
            }
        }
    }
}

// ---------------------------------------------------------------------------
// Tensor-core causal flash attention, bf16x3 (validated R7)
// ---------------------------------------------------------------------------
#define KPITCH 72
#define KROW_B (KPITCH * 2)
#define TILE_B (64 * KROW_B)
#define ASTG   (4 * TILE_B)
#define ATTN_SMEM (2 * ASTG)

__global__ __launch_bounds__(128, 2)
void attn_mma(const __nv_bfloat16* __restrict__ Qh, const __nv_bfloat16* __restrict__ Ql,
              const __nv_bfloat16* __restrict__ Kh, const __nv_bfloat16* __restrict__ Kl,
              const __nv_bfloat16* __restrict__ Vh, const __nv_bfloat16* __restrict__ Vl,
              __nv_bfloat16* __restrict__ Oh, __nv_bfloat16* __restrict__ Ol)
{
    extern __shared__ char smraw[];
    const uint32_t sb0 = smem_u32(smraw);
    const int t = threadIdx.x, lane = t & 31, w = t >> 5;
    const int qb = gridDim.x - 1 - blockIdx.x;
    const int h = blockIdx.y, b = blockIdx.z;
    const size_t bh = (size_t)b * S_ * D_ + (size_t)h * HD_;
    const int q0 = qb * 64;

    const uint32_t qbuf = sb0 + ASTG;
    #pragma unroll
    for (int it = 0; it < 4; it++) {
        const int idx = it * 128 + t;
        const int r = idx >> 3, c = idx & 7;
        const size_t g = bh + (size_t)(q0 + r) * D_ + c * 8;
        const uint32_t so = (uint32_t)(r * KROW_B + c * 16);
        cp16(qbuf + so,          Qh + g);
        cp16(qbuf + TILE_B + so, Ql + g);
    }
    asm volatile("cp.async.commit_group;" ::: "memory");
    asm volatile("cp.async.wait_group 0;" ::: "memory");
    __syncthreads();

    uint32_t qhf[4][4], qlf[4][4];
    {
        const int mr = w * 16 + (lane & 15);
        #pragma unroll
        for (int ks = 0; ks < 4; ks++) {
            const uint32_t off = (uint32_t)(mr * KROW_B + ks * 32 + (lane >> 4) * 16);
            LDSM_X4(qhf[ks][0], qhf[ks][1], qhf[ks][2], qhf[ks][3], qbuf + off);
            LDSM_X4(qlf[ks][0], qlf[ks][1], qlf[ks][2], qlf[ks][3], qbuf + TILE_B + off);
        }
    }
    __syncthreads();

    auto load_kv = [&](int kb) {
        const uint32_t sb = sb0 + (uint32_t)(kb & 1) * ASTG;
        #pragma unroll
        for (int it = 0; it < 4; it++) {
            const int idx = it * 128 + t;
            const int r = idx >> 3, c = idx & 7;
            const size_t g = bh + (size_t)(kb * 64 + r) * D_ + c * 8;
            const uint32_t so = (uint32_t)(r * KROW_B + c * 16);
            cp16(sb + so,              Kh + g);
            cp16(sb + TILE_B + so,     Kl + g);
            cp16(sb + 2 * TILE_B + so, Vh + g);
            cp16(sb + 3 * TILE_B + so, Vl + g);
        }
        asm volatile("cp.async.commit_group;" ::: "memory");
    };
    load_kv(0);

    const int gr  = lane >> 2;
    const int gc2 = (lane & 3) * 2;
    const int row0g = q0 + w * 16 + gr;
    const int row1g = row0g + 8;

    float m0 = -1e30f, m1 = -1e30f, l0 = 0.f, l1 = 0.f;
    float oa[8][4];
    #pragma unroll
    for (int nf = 0; nf < 8; nf++)
        #pragma unroll
        for (int v = 0; v < 4; v++) oa[nf][v] = 0.f;

    for (int kb = 0; kb <= qb; kb++) {
        if (kb < qb) {
            load_kv(kb + 1);
            asm volatile("cp.async.wait_group 1;" ::: "memory");
        } else {
            asm volatile("cp.async.wait_group 0;" ::: "memory");
        }
        __syncthreads();
        const uint32_t sb = sb0 + (uint32_t)(kb & 1) * ASTG;

        float sa[8][4];
        #pragma unroll
        for (int nf = 0; nf < 8; nf++)
            #pragma unroll
            for (int v = 0; v < 4; v++) sa[nf][v] = 0.f;

        #pragma unroll
        for (int ks = 0; ks < 4; ks++) {
            uint32_t kbh[8][2], kbl[8][2];
            #pragma unroll
            for (int nf16 = 0; nf16 < 4; nf16++) {
                const uint32_t off = (uint32_t)((nf16 * 16 + (lane & 15)) * KROW_B
                                                + ks * 32 + (lane >> 4) * 16);
                uint32_t r0, r1, r2, r3;
                LDSM_X4(r0, r1, r2, r3, sb + off);
                kbh[2 * nf16][0] = r0; kbh[2 * nf16][1] = r2;
                kbh[2 * nf16 + 1][0] = r1; kbh[2 * nf16 + 1][1] = r3;
                LDSM_X4(r0, r1, r2, r3, sb + TILE_B + off);
                kbl[2 * nf16][0] = r0; kbl[2 * nf16][1] = r2;
                kbl[2 * nf16 + 1][0] = r1; kbl[2 * nf16 + 1][1] = r3;
            }
            #pragma unroll
            for (int nf = 0; nf < 8; nf++) {
                mma16816(sa[nf], qhf[ks], kbh[nf]);
                mma16816(sa[nf], qhf[ks], kbl[nf]);
                mma16816(sa[nf], qlf[ks], kbh[nf]);
            }
        }

        #pragma unroll
        for (int nf = 0; nf < 8; nf++)
            #pragma unroll
            for (int v = 0; v < 4; v++) sa[nf][v] *= 0.125f;

        if (kb == qb) {
            #pragma unroll
            for (int nf = 0; nf < 8; nf++) {
                const int col = kb * 64 + nf * 8 + gc2;
                if (col     > row0g) sa[nf][0] = -1e30f;
                if (col + 1 > row0g) sa[nf][1] = -1e30f;
                if (col     > row1g) sa[nf][2] = -1e30f;
                if (col + 1 > row1g) sa[nf][3] = -1e30f;
            }
        }

        float mt0 = sa[0][0], mt1 = sa[0][2];
        #pragma unroll
        for (int nf = 0; nf < 8; nf++) {
            mt0 = fmaxf(mt0, fmaxf(sa[nf][0], sa[nf][1]));
            mt1 = fmaxf(mt1, fmaxf(sa[nf][2], sa[nf][3]));
        }
        mt0 = fmaxf(mt0, __shfl_xor_sync(0xffffffffu, mt0, 1));
        mt0 = fmaxf(mt0, __shfl_xor_sync(0xffffffffu, mt0, 2));
        mt1 = fmaxf(mt1, __shfl_xor_sync(0xffffffffu, mt1, 1));
        mt1 = fmaxf(mt1, __shfl_xor_sync(0xffffffffu, mt1, 2));

        const float mn0 = fmaxf(m0, mt0), mn1 = fmaxf(m1, mt1);
        const float c0 = __expf(m0 - mn0), c1 = __expf(m1 - mn1);
        float s0 = 0.f, s1 = 0.f;
        #pragma unroll
        for (int nf = 0; nf < 8; nf++) {
            sa[nf][0] = __expf(sa[nf][0] - mn0); s0 += sa[nf][0];
            sa[nf][1] = __expf(sa[nf][1] - mn0); s0 += sa[nf][1];
            sa[nf][2] = __expf(sa[nf][2] - mn1); s1 += sa[nf][2];
            sa[nf][3] = __expf(sa[nf][3] - mn1); s1 += sa[nf][3];
        }
        s0 += __shfl_xor_sync(0xffffffffu, s0, 1);
        s0 += __shfl_xor_sync(0xffffffffu, s0, 2);
        s1 += __shfl_xor_sync(0xffffffffu, s1, 1);
        s1 += __shfl_xor_sync(0xffffffffu, s1, 2);
        l0 = l0 * c0 + s0;  l1 = l1 * c1 + s1;
        m0 = mn0;           m1 = mn1;

        #pragma unroll
        for (int nf = 0; nf < 8; nf++) {
            oa[nf][0] *= c0; oa[nf][1] *= c0;
            oa[nf][2] *= c1; oa[nf][3] *= c1;
        }

        #pragma unroll
        for (int ks = 0; ks < 4; ks++) {
            uint32_t ph[4], pl[4];
            ph[0] = pack2(sa[2 * ks][0],     sa[2 * ks][1]);
            pl[0] = pack2_lo(ph[0], sa[2 * ks][0], sa[2 * ks][1]);
            ph[1] = pack2(sa[2 * ks][2],     sa[2 * ks][3]);
            pl[1] = pack2_lo(ph[1], sa[2 * ks][2], sa[2 * ks][3]);
            ph[2] = pack2(sa[2 * ks + 1][0], sa[2 * ks + 1][1]);
            pl[2] = pack2_lo(ph[2], sa[2 * ks + 1][0], sa[2 * ks + 1][1]);
            ph[3] = pack2(sa[2 * ks + 1][2], sa[2 * ks + 1][3]);
            pl[3] = pack2_lo(ph[3], sa[2 * ks + 1][2], sa[2 * ks + 1][3]);

            uint32_t vbh[8][2], vbl[8][2];
            #pragma unroll
            for (int nf16 = 0; nf16 < 4; nf16++) {
                const uint32_t off = (uint32_t)((ks * 16 + (lane & 15)) * KROW_B
                                                + nf16 * 32 + (lane >> 4) * 16);
                LDSM_X4T(vbh[2 * nf16][0], vbh[2 * nf16][1],
                         vbh[2 * nf16 + 1][0], vbh[2 * nf16 + 1][1], sb + 2 * TILE_B + off);
                LDSM_X4T(vbl[2 * nf16][0], vbl[2 * nf16][1],
                         vbl[2 * nf16 + 1][0], vbl[2 * nf16 + 1][1], sb + 3 * TILE_B + off);
            }
            #pragma unroll
            for (int nf = 0; nf < 8; nf++) {
                mma16816(oa[nf], ph, vbh[nf]);
                mma16816(oa[nf], ph, vbl[nf]);
                mma16816(oa[nf], pl, vbh[nf]);
            }
        }
        __syncthreads();
    }

    const float iv0 = 1.f / l0, iv1 = 1.f / l1;
    #pragma unroll
    for (int nf = 0; nf < 8; nf++) {
        const size_t a0 = bh + (size_t)(q0 + w * 16 + gr) * D_ + nf * 8 + gc2;
        const size_t a1 = a0 + 8 * D_;
        const float o00 = oa[nf][0] * iv0, o01 = oa[nf][1] * iv0;
        const float o10 = oa[nf][2] * iv1, o11 = oa[nf][3] * iv1;
        const uint32_t hp0 = pack2(o00, o01);
        const uint32_t hp1 = pack2(o10, o11);
        *(uint32_t*)&Oh[a0] = hp0;
        *(uint32_t*)&Ol[a0] = pack2_lo(hp0, o00, o01);
        *(uint32_t*)&Oh[a1] = hp1;
        *(uint32_t*)&Ol[a1] = pack2_lo(hp1, o10, o11);
    }
}

// ---------------------------------------------------------------------------
extern "C" void kernel_launch(void* const* d_in, const int* in_sizes, int n_in,
                              void* d_out, int out_size)
{
    const float* X  = (const float*)d_in[0];
    const float* Wq = (const float*)d_in[1];
    const float* bq = (const float*)d_in[2];
    const float* Wk = (const float*)d_in[3];
    const float* bk = (const float*)d_in[4];
    const float* Wv = (const float*)d_in[5];
    const float* bv = (const float*)d_in[6];
    const float* Wo = (const float*)d_in[7];
    const float* bo = (const float*)d_in[8];
    float* out = (float*)d_out;

    __nv_bfloat16 *Xh, *Xl, *Wh, *Wl, *Qh, *Ql, *Khb, *Klb, *Vh, *Vl;
    float2* tab;
    cudaGetSymbolAddress((void**)&Xh,  g_Xh);
    cudaGetSymbolAddress((void**)&Xl,  g_Xl);
    cudaGetSymbolAddress((void**)&Wh,  g_Wh);
    cudaGetSymbolAddress((void**)&Wl,  g_Wl);
    cudaGetSymbolAddress((void**)&Qh,  g_Qh);
    cudaGetSymbolAddress((void**)&Ql,  g_Ql);
    cudaGetSymbolAddress((void**)&Khb, g_Kh);
    cudaGetSymbolAddress((void**)&Klb, g_Kl);
    cudaGetSymbolAddress((void**)&Vh,  g_Vh);
    cudaGetSymbolAddress((void**)&Vl,  g_Vl);
    cudaGetSymbolAddress((void**)&tab, g_tab);
    const size_t WSZ = (size_t)D_ * D_;

    const int M = B_ * S_;
    const int nvec4 = M * D_ / 4;
    const int wvec4 = D_ * D_ / 4;

    // 0: weight splits (one launch)
    split_w4<<<dim3(wvec4 / 256, 4), 256>>>((const float4*)Wq, (const float4*)Wk,
                                            (const float4*)Wv, (const float4*)Wo, Wh, Wl);
    // 1: rope table
    rope_table<<<(S_ * (D_ / 2)) / 256, 256>>>(tab);
    // 2: X split
    split_bf16<<<nvec4 / 256, 256>>>((const float4*)X, Xh, Xl);

    // 3-5: projections with fused epilogues
    cudaFuncSetAttribute(gemm_bf16x3<0>, cudaFuncAttributeMaxDynamicSharedMemorySize, GEMM_SMEM);
    cudaFuncSetAttribute(gemm_bf16x3<1>, cudaFuncAttributeMaxDynamicSharedMemorySize, GEMM_SMEM);
    cudaFuncSetAttribute(gemm_bf16x3<2>, cudaFuncAttributeMaxDynamicSharedMemorySize, GEMM_SMEM);
    dim3 ggrid(D_ / BN, M / BM);
    gemm_bf16x3<1><<<ggrid, 256, GEMM_SMEM>>>(Xh, Xl, Wh + 0 * WSZ, Wl + 0 * WSZ, bq,
                                              nullptr, Qh, Ql, tab, M, D_, D_);
    gemm_bf16x3<1><<<ggrid, 256, GEMM_SMEM>>>(Xh, Xl, Wh + 1 * WSZ, Wl + 1 * WSZ, bk,
                                              nullptr, Khb, Klb, tab, M, D_, D_);
    gemm_bf16x3<2><<<ggrid, 256, GEMM_SMEM>>>(Xh, Xl, Wh + 2 * WSZ, Wl + 2 * WSZ, bv,
                                              nullptr, Vh, Vl, nullptr, M, D_, D_);

    // 6: attention (writes bf16 hi/lo into Xh/Xl)
    cudaFuncSetAttribute(attn_mma, cudaFuncAttributeMaxDynamicSharedMemorySize, ATTN_SMEM);
    attn_mma<<<dim3(S_ / 64, H_, B_), 128, ATTN_SMEM>>>(Qh, Ql, Khb, Klb, Vh, Vl, Xh, Xl);

    // 7: output projection
    gemm_bf16x3<0><<<ggrid, 256, GEMM_SMEM>>>(Xh, Xl, Wh + 3 * WSZ, Wl + 3 * WSZ, bo,
                                              out, nullptr, nullptr, nullptr, M, D_, D_);
}

// round 11
// speedup vs baseline: 5.9643x; 1.1173x over previous
#include <cuda_runtime.h>
#include <cuda_bf16.h>
#include <cstdint>
#include <math.h>

#define B_  4
#define S_  2048
#define D_  1024
#define H_  16
#define HD_ 64

// ---------------------------------------------------------------------------
// Scratch (__device__ globals: allocation-free rule)
// ---------------------------------------------------------------------------
__device__ __nv_bfloat16 g_Xh[(size_t)B_ * S_ * D_];   // X hi, later attn-out hi
__device__ __nv_bfloat16 g_Xl[(size_t)B_ * S_ * D_];
__device__ __nv_bfloat16 g_Qh[(size_t)B_ * S_ * D_];
__device__ __nv_bfloat16 g_Ql[(size_t)B_ * S_ * D_];
__device__ __nv_bfloat16 g_Kh[(size_t)B_ * S_ * D_];
__device__ __nv_bfloat16 g_Kl[(size_t)B_ * S_ * D_];
__device__ __nv_bfloat16 g_Vh[(size_t)B_ * S_ * D_];
__device__ __nv_bfloat16 g_Vl[(size_t)B_ * S_ * D_];
__device__ __nv_bfloat16 g_Wh[4][(size_t)D_ * D_];
__device__ __nv_bfloat16 g_Wl[4][(size_t)D_ * D_];
__device__ float2 g_tab[(size_t)S_ * (D_ / 2)];

__device__ __forceinline__ uint32_t smem_u32(const void* p) {
    uint32_t a;
    asm("{ .reg .u64 t; cvta.to.shared.u64 t, %1; cvt.u32.u64 %0, t; }" : "=r"(a) : "l"(p));
    return a;
}
__device__ __forceinline__ void cp16(uint32_t s, const void* g) {
    asm volatile("cp.async.cg.shared.global [%0], [%1], 16;" :: "r"(s), "l"(g) : "memory");
}
#define LDSM_X4(r0, r1, r2, r3, a)                                              \
    asm volatile("ldmatrix.sync.aligned.m8n8.x4.shared.b16 {%0,%1,%2,%3}, [%4];" \
        : "=r"(r0), "=r"(r1), "=r"(r2), "=r"(r3) : "r"(a))
#define LDSM_X4T(r0, r1, r2, r3, a)                                                   \
    asm volatile("ldmatrix.sync.aligned.m8n8.x4.trans.shared.b16 {%0,%1,%2,%3}, [%4];" \
        : "=r"(r0), "=r"(r1), "=r"(r2), "=r"(r3) : "r"(a))

__device__ __forceinline__ void mma16816(float* d, const uint32_t* a, const uint32_t* b) {
    asm volatile(
        "mma.sync.aligned.m16n8k16.row.col.f32.bf16.bf16.f32 "
        "{%0,%1,%2,%3}, {%4,%5,%6,%7}, {%8,%9}, {%0,%1,%2,%3};"
        : "+f"(d[0]), "+f"(d[1]), "+f"(d[2]), "+f"(d[3])
        : "r"(a[0]), "r"(a[1]), "r"(a[2]), "r"(a[3]), "r"(b[0]), "r"(b[1]));
}

__device__ __forceinline__ uint32_t pack2(float lo, float hi) {
    uint32_t r;
    asm("cvt.rn.bf16x2.f32 %0, %1, %2;" : "=r"(r) : "f"(hi), "f"(lo));
    return r;
}
__device__ __forceinline__ uint32_t pack2_lo(uint32_t hp, float v0, float v1) {
    float r0 = v0 - __uint_as_float(hp << 16);
    float r1 = v1 - __uint_as_float(hp & 0xffff0000u);
    return pack2(r0, r1);
}

// ---------------------------------------------------------------------------
__global__ void rope_table(float2* __restrict__ tab)
{
    const int idx = blockIdx.x * blockDim.x + threadIdx.x;
    const int p = idx & (D_ / 2 - 1);
    const int s = idx >> 9;
    const float inv = exp2f((float)p * (-13.287712379549449f / (float)(D_ / 2)));
    float sn, c;
    sincosf((float)s * inv, &sn, &c);
    tab[idx] = make_float2(c, sn);
}

__global__ void split_bf16(const float4* __restrict__ src,
                           __nv_bfloat16* __restrict__ hi,
                           __nv_bfloat16* __restrict__ lo)
{
    const int i = blockIdx.x * blockDim.x + threadIdx.x;
    float4 x = src[i];
    uint2 h, l;
    h.x = pack2(x.x, x.y); l.x = pack2(x.x - __uint_as_float(h.x << 16),
                                       x.y - __uint_as_float(h.x & 0xffff0000u));
    h.y = pack2(x.z, x.w); l.y = pack2(x.z - __uint_as_float(h.y << 16),
                                       x.w - __uint_as_float(h.y & 0xffff0000u));
    *(uint2*)&hi[(size_t)i * 4] = h;
    *(uint2*)&lo[(size_t)i * 4] = l;
}

__global__ void split_w4(const float4* __restrict__ w0, const float4* __restrict__ w1,
                         const float4* __restrict__ w2, const float4* __restrict__ w3,
                         __nv_bfloat16* __restrict__ hi, __nv_bfloat16* __restrict__ lo)
{
    const int m = blockIdx.y;
    const float4* src = (m == 0) ? w0 : (m == 1) ? w1 : (m == 2) ? w2 : w3;
    const int i = blockIdx.x * blockDim.x + threadIdx.x;
    const size_t off = (size_t)m * D_ * D_ + (size_t)i * 4;
    float4 x = src[i];
    uint2 h, l;
    h.x = pack2(x.x, x.y); l.x = pack2(x.x - __uint_as_float(h.x << 16),
                                       x.y - __uint_as_float(h.x & 0xffff0000u));
    h.y = pack2(x.z, x.w); l.y = pack2(x.z - __uint_as_float(h.y << 16),
                                       x.w - __uint_as_float(h.y & 0xffff0000u));
    *(uint2*)&hi[off] = h;
    *(uint2*)&lo[off] = l;
}

// ---------------------------------------------------------------------------
// GEMM tiles / pipeline constants
// ---------------------------------------------------------------------------
#define BM 128
#define BN 128
#define BK 32
#define APITCH 40
#define BPITCH 136
#define A_BYTES (BM * APITCH * 2)
#define B_BYTES (BK * BPITCH * 2)
#define STG     (2 * A_BYTES + 2 * B_BYTES)   // 37888
#define NSTAGE  3
#define GEMM_SMEM (NSTAGE * STG)              // 113664

// Shared mainloop: accumulates bf16x3 C tile into acc[4][4][4].
// Single __syncthreads per chunk; A-fragment register rotation.
#define GEMM_MAINLOOP(Ah, Al, Bh, Bl)                                                     \
    auto load_stage = [&](int s, int k0) {                                                \
        const uint32_t sbst = sbase + (uint32_t)s * STG;                                  \
        _Pragma("unroll")                                                                 \
        for (int it = 0; it < 2; it++) {                                                  \
            const int idx = it * 256 + t;                                                 \
            const int m   = idx >> 2;                                                     \
            const int ca  = idx & 3;                                                      \
            const size_t ga = (size_t)(row0 + m) * 1024 + k0 + ca * 8;                    \
            const uint32_t soa = (uint32_t)(m * APITCH * 2 + ca * 16);                    \
            cp16(sbst + soa,           Ah + ga);                                          \
            cp16(sbst + A_BYTES + soa, Al + ga);                                          \
            const int kr = idx >> 4;                                                      \
            const int cb = idx & 15;                                                      \
            const size_t gb = (size_t)(k0 + kr) * 1024 + col0 + cb * 8;                   \
            const uint32_t sob = (uint32_t)(kr * BPITCH * 2 + cb * 16);                   \
            cp16(sbst + 2 * A_BYTES + sob,           Bh + gb);                            \
            cp16(sbst + 2 * A_BYTES + B_BYTES + sob, Bl + gb);                            \
        }                                                                                 \
        asm volatile("cp.async.commit_group;" ::: "memory");                              \
    };                                                                                    \
    const int NCH = 1024 / BK;                                                            \
    load_stage(0, 0);                                                                     \
    load_stage(1, BK);                                                                    \
    for (int ch = 0; ch < NCH; ch++) {                                                    \
        if (ch + 1 < NCH) asm volatile("cp.async.wait_group 1;" ::: "memory");            \
        else              asm volatile("cp.async.wait_group 0;" ::: "memory");            \
        __syncthreads();                                                                  \
        if (ch + 2 < NCH) load_stage((ch + 2) % NSTAGE, (ch + 2) * BK);                   \
        const uint32_t sb  = sbase + (uint32_t)(ch % NSTAGE) * STG;                       \
        const uint32_t aAh = sb;                                                          \
        const uint32_t aAl = sb + A_BYTES;                                                \
        const uint32_t aBh = sb + 2 * A_BYTES;                                            \
        const uint32_t aBl = aBh + B_BYTES;                                               \
        _Pragma("unroll")                                                                 \
        for (int ks = 0; ks < 2; ks++) {                                                  \
            uint32_t bh[4][2], bl[4][2];                                                  \
            const int kr = ks * 16 + (lane & 15);                                         \
            const int nc = wn * 32 + (lane >> 4) * 8;                                     \
            _Pragma("unroll")                                                             \
            for (int jp = 0; jp < 2; jp++) {                                              \
                const uint32_t off = (uint32_t)((kr * BPITCH + nc + jp * 16) * 2);        \
                LDSM_X4T(bh[2*jp][0], bh[2*jp][1], bh[2*jp+1][0], bh[2*jp+1][1], aBh+off);\
                LDSM_X4T(bl[2*jp][0], bl[2*jp][1], bl[2*jp+1][0], bl[2*jp+1][1], aBl+off);\
            }                                                                             \
            uint32_t ah2[2][4], al2[2][4];                                                \
            const int mr = wm * 64 + (lane & 15);                                         \
            const int kc = ks * 16 + (lane >> 4) * 8;                                     \
            {                                                                             \
                const uint32_t off = (uint32_t)((mr * APITCH + kc) * 2);                  \
                LDSM_X4(ah2[0][0], ah2[0][1], ah2[0][2], ah2[0][3], aAh + off);           \
                LDSM_X4(al2[0][0], al2[0][1], al2[0][2], al2[0][3], aAl + off);           \
            }                                                                             \
            _Pragma("unroll")                                                             \
            for (int i = 0; i < 4; i++) {                                                 \
                if (i < 3) {                                                              \
                    const uint32_t off = (uint32_t)(((mr + (i+1)*16) * APITCH + kc) * 2); \
                    LDSM_X4(ah2[(i+1)&1][0], ah2[(i+1)&1][1],                             \
                            ah2[(i+1)&1][2], ah2[(i+1)&1][3], aAh + off);                 \
                    LDSM_X4(al2[(i+1)&1][0], al2[(i+1)&1][1],                             \
                            al2[(i+1)&1][2], al2[(i+1)&1][3], aAl + off);                 \
                }                                                                         \
                _Pragma("unroll")                                                         \
                for (int j = 0; j < 4; j++) {                                             \
                    mma16816(acc[i][j], ah2[i&1], bh[j]);                                 \
                    mma16816(acc[i][j], ah2[i&1], bl[j]);                                 \
                    mma16816(acc[i][j], al2[i&1], bh[j]);                                 \
                }                                                                         \
            }                                                                             \
        }                                                                                 \
    }

// ---------------------------------------------------------------------------
// Fused Q/K/V projection GEMM. blockIdx.z selects weight/bias/output.
// z<2: RoPE + bf16 hi/lo epilogue; z==2: plain bf16 hi/lo epilogue.
// ---------------------------------------------------------------------------
__global__ __launch_bounds__(256)
void gemm_qkv(const __nv_bfloat16* __restrict__ Ah, const __nv_bfloat16* __restrict__ Al,
              const __nv_bfloat16* __restrict__ Whb, const __nv_bfloat16* __restrict__ Wlb,
              const float* __restrict__ bq, const float* __restrict__ bk,
              const float* __restrict__ bv,
              __nv_bfloat16* __restrict__ Qh, __nv_bfloat16* __restrict__ Ql,
              __nv_bfloat16* __restrict__ Kh, __nv_bfloat16* __restrict__ Kl,
              __nv_bfloat16* __restrict__ Vh, __nv_bfloat16* __restrict__ Vl,
              const float2* __restrict__ tab)
{
    extern __shared__ char smraw[];
    const uint32_t sbase = smem_u32(smraw);
    const int t    = threadIdx.x;
    const int lane = t & 31;
    const int wid  = t >> 5;
    const int wm   = wid & 1;
    const int wn   = wid >> 1;
    const int row0 = blockIdx.y * BM;
    const int col0 = blockIdx.x * BN;
    const int z    = blockIdx.z;

    const size_t WSZ = (size_t)D_ * D_;
    const __nv_bfloat16* Bh = Whb + (size_t)z * WSZ;
    const __nv_bfloat16* Bl = Wlb + (size_t)z * WSZ;
    const float* bias = (z == 0) ? bq : (z == 1) ? bk : bv;
    __nv_bfloat16* Oh = (z == 0) ? Qh : (z == 1) ? Kh : Vh;
    __nv_bfloat16* Ol = (z == 0) ? Ql : (z == 1) ? Kl : Vl;

    float acc[4][4][4];
    #pragma unroll
    for (int i = 0; i < 4; i++)
        #pragma unroll
        for (int j = 0; j < 4; j++)
            #pragma unroll
            for (int v = 0; v < 4; v++) acc[i][j][v] = 0.f;

    GEMM_MAINLOOP(Ah, Al, Bh, Bl)

    // epilogue
    const int gr = lane >> 2;
    const int gc = (lane & 3) * 2;
    const bool do_rope = (z < 2);
    #pragma unroll
    for (int i = 0; i < 4; i++) {
        const int r0g = row0 + wm * 64 + i * 16 + gr;
        const int r1g = r0g + 8;
        #pragma unroll
        for (int j = 0; j < 4; j++) {
            const int c = col0 + wn * 32 + j * 8 + gc;
            const float b0 = bias[c], b1 = bias[c + 1];
            float v00 = acc[i][j][0] + b0, v01 = acc[i][j][1] + b1;
            float v10 = acc[i][j][2] + b0, v11 = acc[i][j][3] + b1;
            if (do_rope) {
                const int p = c >> 1;
                const float2 cs0 = tab[(size_t)(r0g & (S_ - 1)) * (D_ / 2) + p];
                const float2 cs1 = tab[(size_t)(r1g & (S_ - 1)) * (D_ / 2) + p];
                float t0 = v00 * cs0.x - v01 * cs0.y;
                float t1 = v00 * cs0.y + v01 * cs0.x;
                v00 = t0; v01 = t1;
                t0 = v10 * cs1.x - v11 * cs1.y;
                t1 = v10 * cs1.y + v11 * cs1.x;
                v10 = t0; v11 = t1;
            }
            const size_t a0 = (size_t)r0g * D_ + c;
            const size_t a1 = (size_t)r1g * D_ + c;
            const uint32_t h0 = pack2(v00, v01);
            const uint32_t h1 = pack2(v10, v11);
            *(uint32_t*)&Oh[a0] = h0;
            *(uint32_t*)&Ol[a0] = pack2_lo(h0, v00, v01);
            *(uint32_t*)&Oh[a1] = h1;
            *(uint32_t*)&Ol[a1] = pack2_lo(h1, v10, v11);
        }
    }
}

// ---------------------------------------------------------------------------
// Output projection GEMM (fp32 epilogue)
// ---------------------------------------------------------------------------
__global__ __launch_bounds__(256)
void gemm_out(const __nv_bfloat16* __restrict__ Ah, const __nv_bfloat16* __restrict__ Al,
              const __nv_bfloat16* __restrict__ Bh, const __nv_bfloat16* __restrict__ Bl,
              const float* __restrict__ bias, float* __restrict__ C)
{
    extern __shared__ char smraw[];
    const uint32_t sbase = smem_u32(smraw);
    const int t    = threadIdx.x;
    const int lane = t & 31;
    const int wid  = t >> 5;
    const int wm   = wid & 1;
    const int wn   = wid >> 1;
    const int row0 = blockIdx.y * BM;
    const int col0 = blockIdx.x * BN;

    float acc[4][4][4];
    #pragma unroll
    for (int i = 0; i < 4; i++)
        #pragma unroll
        for (int j = 0; j < 4; j++)
            #pragma unroll
            for (int v = 0; v < 4; v++) acc[i][j][v] = 0.f;

    GEMM_MAINLOOP(Ah, Al, Bh, Bl)

    const int gr = lane >> 2;
    const int gc = (lane & 3) * 2;
    #pragma unroll
    for (int i = 0; i < 4; i++) {
        const int r0g = row0 + wm * 64 + i * 16 + gr;
        const int r1g = r0g + 8;
        #pragma unroll
        for (int j = 0; j < 4; j++) {
            const int c = col0 + wn * 32 + j * 8 + gc;
            const float b0 = bias[c], b1 = bias[c + 1];
            *(float2*)&C[(size_t)r0g * D_ + c] =
                make_float2(acc[i][j][0] + b0, acc[i][j][1] + b1);
            *(float2*)&C[(size_t)r1g * D_ + c] =
                make_float2(acc[i][j][2] + b0, acc[i][j][3] + b1);
        }
    }
}

// ---------------------------------------------------------------------------
// Tensor-core causal flash attention, bf16x3. Single sync per K-block,
// occupancy 3.
// ---------------------------------------------------------------------------
#define KPITCH 72
#define KROW_B (KPITCH * 2)
#define TILE_B (64 * KROW_B)
#define ASTG   (4 * TILE_B)
#define ATTN_SMEM (2 * ASTG)

__global__ __launch_bounds__(128, 3)
void attn_mma(const __nv_bfloat16* __restrict__ Qh, const __nv_bfloat16* __restrict__ Ql,
              const __nv_bfloat16* __restrict__ Kh, const __nv_bfloat16* __restrict__ Kl,
              const __nv_bfloat16* __restrict__ Vh, const __nv_bfloat16* __restrict__ Vl,
              __nv_bfloat16* __restrict__ Oh, __nv_bfloat16* __restrict__ Ol)
{
    extern __shared__ char smraw[];
    const uint32_t sb0 = smem_u32(smraw);
    const int t = threadIdx.x, lane = t & 31, w = t >> 5;
    const int qb = gridDim.x - 1 - blockIdx.x;
    const int h = blockIdx.y, b = blockIdx.z;
    const size_t bh = (size_t)b * S_ * D_ + (size_t)h * HD_;
    const int q0 = qb * 64;

    auto load_kv = [&](int kb) {
        const uint32_t sb = sb0 + (uint32_t)(kb & 1) * ASTG;
        #pragma unroll
        for (int it = 0; it < 4; it++) {
            const int idx = it * 128 + t;
            const int r = idx >> 3, c = idx & 7;
            const size_t g = bh + (size_t)(kb * 64 + r) * D_ + c * 8;
            const uint32_t so = (uint32_t)(r * KROW_B + c * 16);
            cp16(sb + so,              Kh + g);
            cp16(sb + TILE_B + so,     Kl + g);
            cp16(sb + 2 * TILE_B + so, Vh + g);
            cp16(sb + 3 * TILE_B + so, Vl + g);
        }
        asm volatile("cp.async.commit_group;" ::: "memory");
    };

    // Q stage into stage-1 buffer; overlap with kv(0) load
    const uint32_t qbuf = sb0 + ASTG;
    #pragma unroll
    for (int it = 0; it < 4; it++) {
        const int idx = it * 128 + t;
        const int r = idx >> 3, c = idx & 7;
        const size_t g = bh + (size_t)(q0 + r) * D_ + c * 8;
        const uint32_t so = (uint32_t)(r * KROW_B + c * 16);
        cp16(qbuf + so,          Qh + g);
        cp16(qbuf + TILE_B + so, Ql + g);
    }
    asm volatile("cp.async.commit_group;" ::: "memory");
    load_kv(0);
    asm volatile("cp.async.wait_group 1;" ::: "memory");   // Q landed
    __syncthreads();

    uint32_t qhf[4][4], qlf[4][4];
    {
        const int mr = w * 16 + (lane & 15);
        #pragma unroll
        for (int ks = 0; ks < 4; ks++) {
            const uint32_t off = (uint32_t)(mr * KROW_B + ks * 32 + (lane >> 4) * 16);
            LDSM_X4(qhf[ks][0], qhf[ks][1], qhf[ks][2], qhf[ks][3], qbuf + off);
            LDSM_X4(qlf[ks][0], qlf[ks][1], qlf[ks][2], qlf[ks][3], qbuf + TILE_B + off);
        }
    }
    __syncthreads();   // all warps done reading qbuf (stage-1) before kv(1) overwrites

    const int gr  = lane >> 2;
    const int gc2 = (lane & 3) * 2;
    const int row0g = q0 + w * 16 + gr;
    const int row1g = row0g + 8;

    float m0 = -1e30f, m1 = -1e30f, l0 = 0.f, l1 = 0.f;
    float oa[8][4];
    #pragma unroll
    for (int nf = 0; nf < 8; nf++)
        #pragma unroll
        for (int v = 0; v < 4; v++) oa[nf][v] = 0.f;

    for (int kb = 0; kb <= qb; kb++) {
        asm volatile("cp.async.wait_group 0;" ::: "memory");
        __syncthreads();
        if (kb < qb) load_kv(kb + 1);
        const uint32_t sb = sb0 + (uint32_t)(kb & 1) * ASTG;

        float sa[8][4];
        #pragma unroll
        for (int nf = 0; nf < 8; nf++)
            #pragma unroll
            for (int v = 0; v < 4; v++) sa[nf][v] = 0.f;

        #pragma unroll
        for (int ks = 0; ks < 4; ks++) {
            uint32_t kbh[8][2], kbl[8][2];
            #pragma unroll
            for (int nf16 = 0; nf16 < 4; nf16++) {
                const uint32_t off = (uint32_t)((nf16 * 16 + (lane & 15)) * KROW_B
                                                + ks * 32 + (lane >> 4) * 16);
                uint32_t r0, r1, r2, r3;
                LDSM_X4(r0, r1, r2, r3, sb + off);
                kbh[2 * nf16][0] = r0; kbh[2 * nf16][1] = r2;
                kbh[2 * nf16 + 1][0] = r1; kbh[2 * nf16 + 1][1] = r3;
                LDSM_X4(r0, r1, r2, r3, sb + TILE_B + off);
                kbl[2 * nf16][0] = r0; kbl[2 * nf16][1] = r2;
                kbl[2 * nf16 + 1][0] = r1; kbl[2 * nf16 + 1][1] = r3;
            }
            #pragma unroll
            for (int nf = 0; nf < 8; nf++) {
                mma16816(sa[nf], qhf[ks], kbh[nf]);
                mma16816(sa[nf], qhf[ks], kbl[nf]);
                mma16816(sa[nf], qlf[ks], kbh[nf]);
            }
        }

        #pragma unroll
        for (int nf = 0; nf < 8; nf++)
            #pragma unroll
            for (int v = 0; v < 4; v++) sa[nf][v] *= 0.125f;

        if (kb == qb) {
            #pragma unroll
            for (int nf = 0; nf < 8; nf++) {
                const int col = kb * 64 + nf * 8 + gc2;
                if (col     > row0g) sa[nf][0] = -1e30f;
                if (col + 1 > row0g) sa[nf][1] = -1e30f;
                if (col     > row1g) sa[nf][2] = -1e30f;
                if (col + 1 > row1g) sa[nf][3] = -1e30f;
            }
        }

        float mt0 = sa[0][0], mt1 = sa[0][2];
        #pragma unroll
        for (int nf = 0; nf < 8; nf++) {
            mt0 = fmaxf(mt0, fmaxf(sa[nf][0], sa[nf][1]));
            mt1 = fmaxf(mt1, fmaxf(sa[nf][2], sa[nf][3]));
        }
        mt0 = fmaxf(mt0, __shfl_xor_sync(0xffffffffu, mt0, 1));
        mt0 = fmaxf(mt0, __shfl_xor_sync(0xffffffffu, mt0, 2));
        mt1 = fmaxf(mt1, __shfl_xor_sync(0xffffffffu, mt1, 1));
        mt1 = fmaxf(mt1, __shfl_xor_sync(0xffffffffu, mt1, 2));

        const float mn0 = fmaxf(m0, mt0), mn1 = fmaxf(m1, mt1);
        const float c0 = __expf(m0 - mn0), c1 = __expf(m1 - mn1);
        float s0 = 0.f, s1 = 0.f;
        #pragma unroll
        for (int nf = 0; nf < 8; nf++) {
            sa[nf][0] = __expf(sa[nf][0] - mn0); s0 += sa[nf][0];
            sa[nf][1] = __expf(sa[nf][1] - mn0); s0 += sa[nf][1];
            sa[nf][2] = __expf(sa[nf][2] - mn1); s1 += sa[nf][2];
            sa[nf][3] = __expf(sa[nf][3] - mn1); s1 += sa[nf][3];
        }
        s0 += __shfl_xor_sync(0xffffffffu, s0, 1);
        s0 += __shfl_xor_sync(0xffffffffu, s0, 2);
        s1 += __shfl_xor_sync(0xffffffffu, s1, 1);
        s1 += __shfl_xor_sync(0xffffffffu, s1, 2);
        l0 = l0 * c0 + s0;  l1 = l1 * c1 + s1;
        m0 = mn0;           m1 = mn1;

        #pragma unroll
        for (int nf = 0; nf < 8; nf++) {
            oa[nf][0] *= c0; oa[nf][1] *= c0;
            oa[nf][2] *= c1; oa[nf][3] *= c1;
        }

        #pragma unroll
        for (int ks = 0; ks < 4; ks++) {
            uint32_t ph[4], pl[4];
            ph[0] = pack2(sa[2 * ks][0],     sa[2 * ks][1]);
            pl[0] = pack2_lo(ph[0], sa[2 * ks][0], sa[2 * ks][1]);
            ph[1] = pack2(sa[2 * ks][2],     sa[2 * ks][3]);
            pl[1] = pack2_lo(ph[1], sa[2 * ks][2], sa[2 * ks][3]);
            ph[2] = pack2(sa[2 * ks + 1][0], sa[2 * ks + 1][1]);
            pl[2] = pack2_lo(ph[2], sa[2 * ks + 1][0], sa[2 * ks + 1][1]);
            ph[3] = pack2(sa[2 * ks + 1][2], sa[2 * ks + 1][3]);
            pl[3] = pack2_lo(ph[3], sa[2 * ks + 1][2], sa[2 * ks + 1][3]);

            uint32_t vbh[8][2], vbl[8][2];
            #pragma unroll
            for (int nf16 = 0; nf16 < 4; nf16++) {
                const uint32_t off = (uint32_t)((ks * 16 + (lane & 15)) * KROW_B
                                                + nf16 * 32 + (lane >> 4) * 16);
                LDSM_X4T(vbh[2 * nf16][0], vbh[2 * nf16][1],
                         vbh[2 * nf16 + 1][0], vbh[2 * nf16 + 1][1], sb + 2 * TILE_B + off);
                LDSM_X4T(vbl[2 * nf16][0], vbl[2 * nf16][1],
                         vbl[2 * nf16 + 1][0], vbl[2 * nf16 + 1][1], sb + 3 * TILE_B + off);
            }
            #pragma unroll
            for (int nf = 0; nf < 8; nf++) {
                mma16816(oa[nf], ph, vbh[nf]);
                mma16816(oa[nf], ph, vbl[nf]);
                mma16816(oa[nf], pl, vbh[nf]);
            }
        }
    }

    const float iv0 = 1.f / l0, iv1 = 1.f / l1;
    #pragma unroll
    for (int nf = 0; nf < 8; nf++) {
        const size_t a0 = bh + (size_t)(q0 + w * 16 + gr) * D_ + nf * 8 + gc2;
        const size_t a1 = a0 + 8 * D_;
        const float o00 = oa[nf][0] * iv0, o01 = oa[nf][1] * iv0;
        const float o10 = oa[nf][2] * iv1, o11 = oa[nf][3] * iv1;
        const uint32_t hp0 = pack2(o00, o01);
        const uint32_t hp1 = pack2(o10, o11);
        *(uint32_t*)&Oh[a0] = hp0;
        *(uint32_t*)&Ol[a0] = pack2_lo(hp0, o00, o01);
        *(uint32_t*)&Oh[a1] = hp1;
        *(uint32_t*)&Ol[a1] = pack2_lo(hp1, o10, o11);
    }
}

// ---------------------------------------------------------------------------
extern "C" void kernel_launch(void* const* d_in, const int* in_sizes, int n_in,
                              void* d_out, int out_size)
{
    const float* X  = (const float*)d_in[0];
    const float* Wq = (const float*)d_in[1];
    const float* bq = (const float*)d_in[2];
    const float* Wk = (const float*)d_in[3];
    const float* bk = (const float*)d_in[4];
    const float* Wv = (const float*)d_in[5];
    const float* bv = (const float*)d_in[6];
    const float* Wo = (const float*)d_in[7];
    const float* bo = (const float*)d_in[8];
    float* out = (float*)d_out;

    __nv_bfloat16 *Xh, *Xl, *Wh, *Wl, *Qh, *Ql, *Khb, *Klb, *Vh, *Vl;
    float2* tab;
    cudaGetSymbolAddress((void**)&Xh,  g_Xh);
    cudaGetSymbolAddress((void**)&Xl,  g_Xl);
    cudaGetSymbolAddress((void**)&Wh,  g_Wh);
    cudaGetSymbolAddress((void**)&Wl,  g_Wl);
    cudaGetSymbolAddress((void**)&Qh,  g_Qh);
    cudaGetSymbolAddress((void**)&Ql,  g_Ql);
    cudaGetSymbolAddress((void**)&Khb, g_Kh);
    cudaGetSymbolAddress((void**)&Klb, g_Kl);
    cudaGetSymbolAddress((void**)&Vh,  g_Vh);
    cudaGetSymbolAddress((void**)&Vl,  g_Vl);
    cudaGetSymbolAddress((void**)&tab, g_tab);
    const size_t WSZ = (size_t)D_ * D_;

    const int M = B_ * S_;
    const int nvec4 = M * D_ / 4;
    const int wvec4 = D_ * D_ / 4;

    split_w4<<<dim3(wvec4 / 256, 4), 256>>>((const float4*)Wq, (const float4*)Wk,
                                            (const float4*)Wv, (const float4*)Wo, Wh, Wl);
    rope_table<<<(S_ * (D_ / 2)) / 256, 256>>>(tab);
    split_bf16<<<nvec4 / 256, 256>>>((const float4*)X, Xh, Xl);

    cudaFuncSetAttribute(gemm_qkv, cudaFuncAttributeMaxDynamicSharedMemorySize, GEMM_SMEM);
    cudaFuncSetAttribute(gemm_out, cudaFuncAttributeMaxDynamicSharedMemorySize, GEMM_SMEM);

    // fused Q/K/V projections
    gemm_qkv<<<dim3(D_ / BN, M / BM, 3), 256, GEMM_SMEM>>>(
        Xh, Xl, Wh, Wl, bq, bk, bv, Qh, Ql, Khb, Klb, Vh, Vl, tab);

    // attention (writes bf16 hi/lo into Xh/Xl)
    cudaFuncSetAttribute(attn_mma, cudaFuncAttributeMaxDynamicSharedMemorySize, ATTN_SMEM);
    attn_mma<<<dim3(S_ / 64, H_, B_), 128, ATTN_SMEM>>>(Qh, Ql, Khb, Klb, Vh, Vl, Xh, Xl);

    // output projection
    gemm_out<<<dim3(D_ / BN, M / BM), 256, GEMM_SMEM>>>(
        Xh, Xl, Wh + 3 * WSZ, Wl + 3 * WSZ, bo, out);
}